// round 12
// baseline (speedup 1.0000x reference)
#include <cuda_runtime.h>
#include <cuda_bf16.h>
#include <math.h>
#include <stdint.h>

#define DIMC   1792
#define M_TOT  16384        // 4 * 64 * 64
#define NCENT  4096
#define HW     4096
#define NB_D   32           // dist n-tiles of 128
#define NB_P   14           // phi  n-tiles of 128
#define KSTEPS 28           // 1792 / 64

// ---------------- scratch ---------------------------------------------------
__device__ __align__(1024) __nv_bfloat16 g_sample_t[(size_t)M_TOT * DIMC];
__device__ __align__(1024) __nv_bfloat16 g_phi_bf[(size_t)M_TOT * DIMC];
__device__ __align__(1024) __nv_bfloat16 g_Ct[(size_t)NCENT * DIMC];
__device__ __align__(1024) __nv_bfloat16 g_Wbf[(size_t)DIMC * DIMC];
__device__ float g_feat2p[M_TOT * NB_P];
__device__ float g_feat2[M_TOT];
__device__ float g_cnorm[NCENT];
__device__ float g_cand[(size_t)M_TOT * NB_D * 6];
__device__ float g_losspart[M_TOT];

// ---------------- helpers ----------------------------------------------------
__device__ __forceinline__ uint32_t smem_u32(const void* p) {
    uint32_t a;
    asm("{ .reg .u64 t; cvta.to.shared.u64 t, %1; cvt.u32.u64 %0, t; }" : "=r"(a) : "l"(p));
    return a;
}
__device__ __forceinline__ void cp16(uint32_t dst, const void* src) {
    asm volatile("cp.async.cg.shared.global [%0], [%1], 16;" :: "r"(dst), "l"(src));
}
__device__ __forceinline__ void insert6(float (&t)[6], float v) {
    if (v < t[5]) {
        t[5] = v;
        #pragma unroll
        for (int j = 5; j > 0; --j)
            if (t[j] < t[j-1]) { float tmp = t[j-1]; t[j-1] = t[j]; t[j] = tmp; }
    }
}

// stage: A(128 rows x 128B) + B(128 rows x 128B) = 32KB; 3 stages = 96KB
#define STG_BYTES 32768
#define B_OFF     16384
#define DYN_SMEM  (3 * STG_BYTES)
// full SW128 swizzle: row r (0..127, 128B pitch), 16B-chunk c (0..7)
__device__ __forceinline__ uint32_t swz(int r, int c) {
    return (uint32_t)(r * 128 + ((c ^ (r & 7)) * 16));
}

__device__ __forceinline__ void load_stage(uint32_t sb, int s,
                                           const __nv_bfloat16* A,
                                           const __nv_bfloat16* B,
                                           int k0, int tid) {
    uint32_t abase = sb + s * STG_BYTES;
    uint32_t bbase = abase + B_OFF;
    #pragma unroll
    for (int i = 0; i < 4; ++i) {           // A: 128 rows x 128B
        int slot = tid + i * 256;
        int r = slot >> 3, c = slot & 7;
        cp16(abase + swz(r, c), (const char*)A + ((size_t)r * DIMC + k0 + c * 8) * 2);
    }
    #pragma unroll
    for (int i = 0; i < 4; ++i) {           // B: 128 rows x 128B
        int slot = tid + i * 256;
        int r = slot >> 3, c = slot & 7;
        cp16(bbase + swz(r, c), (const char*)B + ((size_t)r * DIMC + k0 + c * 8) * 2);
    }
    asm volatile("cp.async.commit_group;" ::: "memory");
}

#define MMA_BF16(ac, a, b0, b1) \
    asm volatile( \
        "mma.sync.aligned.m16n8k16.row.col.f32.bf16.bf16.f32 " \
        "{%0,%1,%2,%3}, {%4,%5,%6,%7}, {%8,%9}, {%0,%1,%2,%3};" \
        : "+f"((ac)[0]), "+f"((ac)[1]), "+f"((ac)[2]), "+f"((ac)[3]) \
        : "r"((a)[0]), "r"((a)[1]), "r"((a)[2]), "r"((a)[3]), \
          "r"(b0), "r"(b1))

#define LDSM_A(dst, addr) \
    asm volatile("ldmatrix.sync.aligned.m8n8.x4.shared.b16 {%0,%1,%2,%3}, [%4];" \
                 : "=r"((dst)[0]), "=r"((dst)[1]), "=r"((dst)[2]), "=r"((dst)[3]) \
                 : "r"(addr))

// ---------------- main GEMM: 128x128 tile, 8 warps (32x64 each), K=1792 ------
// A fragments software-pipelined across ks (double-buffered, indexed ks&1).
__device__ __forceinline__ void gemm_main(const __nv_bfloat16* A,
                                          const __nv_bfloat16* B,
                                          uint32_t sb,
                                          float (&acc)[2][8][4]) {
    int tid = threadIdx.x, lane = tid & 31, w = tid >> 5;
    int wm = w & 3, wn = w >> 2;

    load_stage(sb, 0, A, B, 0, tid);
    load_stage(sb, 1, A, B, 64, tid);
    asm volatile("cp.async.wait_group 1;" ::: "memory");
    __syncthreads();

    for (int kt = 0; kt < KSTEPS; ++kt) {
        int s = kt % 3;
        if (kt + 2 < KSTEPS)
            load_stage(sb, (kt + 2) % 3, A, B, (kt + 2) * 64, tid);
        else
            asm volatile("cp.async.commit_group;" ::: "memory");

        uint32_t abase = sb + s * STG_BYTES;
        uint32_t bbase = abase + B_OFF;

        uint32_t afr[2][2][4];   // [buf][mi][4]
        // prime A for ks=0
        #pragma unroll
        for (int mi = 0; mi < 2; ++mi) {
            int r = wm * 32 + mi * 16 + (lane & 15);
            int c = (lane >> 4);
            LDSM_A(afr[0][mi], abase + swz(r, c));
        }

        #pragma unroll
        for (int ks = 0; ks < 4; ++ks) {
            int cur = ks & 1;
            // prefetch A for ks+1 — flies under this ks's B loads + MMAs
            if (ks < 3) {
                #pragma unroll
                for (int mi = 0; mi < 2; ++mi) {
                    int r = wm * 32 + mi * 16 + (lane & 15);
                    int c = (ks + 1) * 2 + (lane >> 4);
                    LDSM_A(afr[cur ^ 1][mi], abase + swz(r, c));
                }
            }
            // interleaved B loads + dependent MMAs
            #pragma unroll
            for (int nq = 0; nq < 4; ++nq) {
                uint32_t b00, b01, b10, b11;
                int q = lane >> 3;
                int r = wn * 64 + nq * 16 + (q >> 1) * 8 + (lane & 7);
                int c = ks * 2 + (q & 1);
                uint32_t addr = bbase + swz(r, c);
                asm volatile("ldmatrix.sync.aligned.m8n8.x4.shared.b16 {%0,%1,%2,%3}, [%4];"
                             : "=r"(b00), "=r"(b01), "=r"(b10), "=r"(b11)
                             : "r"(addr));
                MMA_BF16(acc[0][nq * 2],     afr[cur][0], b00, b01);
                MMA_BF16(acc[1][nq * 2],     afr[cur][1], b00, b01);
                MMA_BF16(acc[0][nq * 2 + 1], afr[cur][0], b10, b11);
                MMA_BF16(acc[1][nq * 2 + 1], afr[cur][1], b10, b11);
            }
        }
        asm volatile("cp.async.wait_group 1;" ::: "memory");
        __syncthreads();
    }
}

// ---------------- prepass kernels --------------------------------------------
__global__ void convert_W(const float* __restrict__ W) {
    int o = blockIdx.x;
    for (int c = threadIdx.x; c < DIMC; c += 256)
        g_Wbf[(size_t)o * DIMC + c] = __float2bfloat16(W[(size_t)o * 1794 + c]);
}

// tile: 32 hw x 64 c; smem [hw][c] padded; bf16x2 vectorized stores (128B/warp)
__global__ void transpose_sample(const float* __restrict__ S) {
    __shared__ float t[32][65];
    int b = blockIdx.z;
    int hw0 = blockIdx.x * 32, c0 = blockIdx.y * 64;
    int tx = threadIdx.x, ty = threadIdx.y;   // (32, 8)
    const float* src = S + ((size_t)b * DIMC + c0) * HW + hw0;
    #pragma unroll
    for (int i = 0; i < 8; ++i) {
        int cr = ty + i * 8;
        t[tx][cr] = src[(size_t)cr * HW + tx];
    }
    __syncthreads();
    __nv_bfloat16* dst = g_sample_t + ((size_t)b * HW + hw0) * DIMC + c0;
    #pragma unroll
    for (int i = 0; i < 4; ++i) {
        int hw = ty + i * 8;
        __nv_bfloat162 v = __floats2bfloat162_rn(t[hw][tx * 2], t[hw][tx * 2 + 1]);
        *(__nv_bfloat162*)&dst[(size_t)hw * DIMC + tx * 2] = v;
    }
}

__global__ void transpose_C(const float* __restrict__ C) {
    __shared__ float t[32][33];
    int k0 = blockIdx.x * 32, c0 = blockIdx.y * 32;
    int tx = threadIdx.x, ty = threadIdx.y;
    #pragma unroll
    for (int i = 0; i < 4; ++i)
        t[ty + i * 8][tx] = C[(size_t)(c0 + ty + i * 8) * NCENT + k0 + tx];
    __syncthreads();
    #pragma unroll
    for (int i = 0; i < 4; ++i)
        g_Ct[(size_t)(k0 + ty + i * 8) * DIMC + c0 + tx] = __float2bfloat16(t[tx][ty + i * 8]);
}

// warp-per-center, uint4 loads
__global__ void cnorm2_k() {
    int w = threadIdx.x >> 5, lane = threadIdx.x & 31;
    int k = blockIdx.x * 8 + w;
    const uint4* row = (const uint4*)(g_Ct + (size_t)k * DIMC);
    float s = 0.f;
    for (int i = lane; i < 224; i += 32) {
        uint4 v = row[i];
        const __nv_bfloat162* h = (const __nv_bfloat162*)&v;
        #pragma unroll
        for (int j = 0; j < 4; ++j) {
            float2 f = __bfloat1622float2(h[j]);
            s += f.x * f.x + f.y * f.y;
        }
    }
    #pragma unroll
    for (int o = 16; o; o >>= 1) s += __shfl_xor_sync(0xffffffffu, s, o);
    if (lane == 0) g_cnorm[k] = s;
}

// ---------------- phi GEMM (coordconv 1x1) ------------------------------------
__global__ __launch_bounds__(256, 2) void phi_mma(const float* __restrict__ W,
                                                  const float* __restrict__ bias) {
    extern __shared__ __align__(1024) unsigned char smem[];
    uint32_t sb = smem_u32(smem);
    const int n0 = blockIdx.x * 128;
    const int p0 = blockIdx.y * 128;

    float acc[2][8][4] = {};
    gemm_main(g_sample_t + (size_t)p0 * DIMC, g_Wbf + (size_t)n0 * DIMC, sb, acc);

    int tid = threadIdx.x, lane = tid & 31, w = tid >> 5;
    int wm = w & 3, wn = w >> 2, gid = lane >> 2, tq = lane & 3;

    // stage coord weights + bias in smem
    float* smw = (float*)smem;            // [128]wx [128]wy [128]b
    float* smf = (float*)(smem + 2048);   // [128][2]
    if (tid < 128) {
        size_t col = (size_t)(n0 + tid);
        smw[tid]       = __ldg(&W[col * 1794 + 1792]);
        smw[128 + tid] = __ldg(&W[col * 1794 + 1793]);
        smw[256 + tid] = __ldg(&bias[col]);
    }
    __syncthreads();

    #pragma unroll
    for (int mi = 0; mi < 2; ++mi)
        #pragma unroll
        for (int hh = 0; hh < 2; ++hh) {
            int row = wm * 32 + mi * 16 + hh * 8 + gid;
            int p = p0 + row;
            int hw = p & 4095;
            float xx = -1.f + 2.f * (float)(hw & 63) * (1.f / 63.f);
            float yy = -1.f + 2.f * (float)(hw >> 6) * (1.f / 63.f);
            float sq = 0.f;
            #pragma unroll
            for (int ni = 0; ni < 8; ++ni) {
                int ci = wn * 64 + ni * 8 + tq * 2;
                float v0 = acc[mi][ni][hh * 2]     + xx * smw[ci]   + yy * smw[128 + ci]   + smw[256 + ci];
                float v1 = acc[mi][ni][hh * 2 + 1] + xx * smw[ci+1] + yy * smw[128 + ci+1] + smw[256 + ci+1];
                __nv_bfloat162 bb = __floats2bfloat162_rn(v0, v1);
                *(uint32_t*)&g_phi_bf[(size_t)p * DIMC + n0 + ci] = *(uint32_t*)&bb;
                float f0 = __bfloat162float(bb.x), f1 = __bfloat162float(bb.y);
                sq += f0 * f0 + f1 * f1;
            }
            sq += __shfl_xor_sync(0xffffffffu, sq, 1);
            sq += __shfl_xor_sync(0xffffffffu, sq, 2);
            if (tq == 0) smf[row * 2 + wn] = sq;
        }
    __syncthreads();
    if (tid < 128)
        g_feat2p[(size_t)(p0 + tid) * NB_P + blockIdx.x] = smf[tid * 2] + smf[tid * 2 + 1];
}

__global__ void feat2_k() {
    int p = blockIdx.x * 256 + threadIdx.x;
    float s = 0.f;
    #pragma unroll
    for (int i = 0; i < NB_P; ++i) s += g_feat2p[(size_t)p * NB_P + i];
    g_feat2[p] = s;
}

// ---------------- dist GEMM + per-tile top-6 ----------------------------------
__global__ __launch_bounds__(256, 2) void dist_mma() {
    extern __shared__ __align__(1024) unsigned char smem[];
    uint32_t sb = smem_u32(smem);
    const int nb = blockIdx.x;
    const int n0 = nb * 128;
    const int p0 = blockIdx.y * 128;

    float acc[2][8][4] = {};
    gemm_main(g_phi_bf + (size_t)p0 * DIMC, g_Ct + (size_t)n0 * DIMC, sb, acc);

    int tid = threadIdx.x, lane = tid & 31, w = tid >> 5;
    int wm = w & 3, wn = w >> 2, gid = lane >> 2, tq = lane & 3;

    // hoist per-row feat2 into registers before smem staging
    float f2r[2][2];
    #pragma unroll
    for (int mi = 0; mi < 2; ++mi)
        #pragma unroll
        for (int hh = 0; hh < 2; ++hh)
            f2r[mi][hh] = g_feat2[p0 + wm * 32 + mi * 16 + hh * 8 + gid];

    float* smc = (float*)smem;                 // [128] cnorm
    float* sm_t6 = (float*)(smem + 1024);      // [128][2][6]
    if (tid < 128) smc[tid] = g_cnorm[n0 + tid];
    __syncthreads();

    #pragma unroll
    for (int mi = 0; mi < 2; ++mi)
        #pragma unroll
        for (int hh = 0; hh < 2; ++hh) {
            int row = wm * 32 + mi * 16 + hh * 8 + gid;
            float f2 = f2r[mi][hh];
            float t6[6];
            #pragma unroll
            for (int j = 0; j < 6; ++j) t6[j] = 3.4e38f;
            #pragma unroll
            for (int ni = 0; ni < 8; ++ni) {
                int ci = wn * 64 + ni * 8 + tq * 2;
                insert6(t6, f2 + smc[ci]     - 2.f * acc[mi][ni][hh * 2]);
                insert6(t6, f2 + smc[ci + 1] - 2.f * acc[mi][ni][hh * 2 + 1]);
            }
            #pragma unroll
            for (int off = 1; off <= 2; off <<= 1) {
                float o6[6];
                #pragma unroll
                for (int j = 0; j < 6; ++j) o6[j] = __shfl_xor_sync(0xffffffffu, t6[j], off);
                #pragma unroll
                for (int j = 0; j < 6; ++j) insert6(t6, o6[j]);
            }
            if (tq == 0) {
                #pragma unroll
                for (int j = 0; j < 6; ++j) sm_t6[(row * 2 + wn) * 6 + j] = t6[j];
            }
        }
    __syncthreads();
    if (tid < 128) {
        float t6[6];
        #pragma unroll
        for (int j = 0; j < 6; ++j) t6[j] = 3.4e38f;
        #pragma unroll
        for (int v = 0; v < 12; ++v) insert6(t6, sm_t6[tid * 12 + v]);
        size_t base = ((size_t)(p0 + tid) * NB_D + nb) * 6;
        #pragma unroll
        for (int j = 0; j < 6; ++j) g_cand[base + j] = t6[j];
    }
}

// ---------------- topk merge + score + loss -----------------------------------
__global__ void topk_kernel(const float* __restrict__ r_in, float* __restrict__ out) {
    int warp = threadIdx.x >> 5;
    int lane = threadIdx.x & 31;
    int p = blockIdx.x * 4 + warp;
    const float* cand = g_cand + (size_t)p * (NB_D * 6);   // 192 values

    float t6[6];
    #pragma unroll
    for (int j = 0; j < 6; ++j) t6[j] = 3.4e38f;
    #pragma unroll
    for (int j = 0; j < 6; ++j) insert6(t6, cand[lane + 32 * j]);

    #pragma unroll
    for (int off = 16; off > 0; off >>= 1) {
        float o6[6];
        #pragma unroll
        for (int j = 0; j < 6; ++j) o6[j] = __shfl_xor_sync(0xffffffffu, t6[j], off);
        #pragma unroll
        for (int j = 0; j < 6; ++j) insert6(t6, o6[j]);
    }

    if (lane == 0) {
        float rr = r_in[0];
        float r2 = rr * rr;
        float d0 = sqrtf(fmaxf(t6[0], 0.f));
        float d1 = sqrtf(fmaxf(t6[1], 0.f));
        float d2 = sqrtf(fmaxf(t6[2], 0.f));
        float w0 = 1.f / (1.f + expf(d0 - d1) + expf(d0 - d2));
        out[1 + p] = w0 * d0;

        float att = fmaxf(t6[0] - r2, 0.f) + fmaxf(t6[1] - r2, 0.f) + fmaxf(t6[2] - r2, 0.f);
        float rep = fmaxf(r2 - t6[3] - 0.1f, 0.f) + fmaxf(r2 - t6[4] - 0.1f, 0.f)
                  + fmaxf(r2 - t6[5] - 0.1f, 0.f);
        g_losspart[p] = att + rep;
    }
}

__global__ void loss_kernel(float* __restrict__ out) {
    __shared__ float sbuf[256];
    float s = 0.f;
    for (int i = threadIdx.x; i < M_TOT; i += 256) s += g_losspart[i];
    sbuf[threadIdx.x] = s;
    __syncthreads();
    for (int o = 128; o > 0; o >>= 1) {
        if (threadIdx.x < o) sbuf[threadIdx.x] += sbuf[threadIdx.x + o];
        __syncthreads();
    }
    if (threadIdx.x == 0)
        out[0] = sbuf[0] * (1000.f / (float)(M_TOT * 3));
}

// ---------------- launcher ------------------------------------------------------
extern "C" void kernel_launch(void* const* d_in, const int* in_sizes, int n_in,
                              void* d_out, int out_size) {
    const float* sample = (const float*)d_in[0];
    const float* W      = (const float*)d_in[1];
    const float* bias   = (const float*)d_in[2];
    const float* C      = (const float*)d_in[3];
    const float* r      = (const float*)d_in[4];
    float* out = (float*)d_out;

    cudaFuncSetAttribute(phi_mma, cudaFuncAttributeMaxDynamicSharedMemorySize, DYN_SMEM);
    cudaFuncSetAttribute(dist_mma, cudaFuncAttributeMaxDynamicSharedMemorySize, DYN_SMEM);

    // phi_mma stays at launch index 3 (the ncu sampling slot)
    convert_W<<<DIMC, 256>>>(W);                                        // 0
    transpose_sample<<<dim3(HW / 32, DIMC / 64, 4), dim3(32, 8)>>>(sample); // 1
    transpose_C<<<dim3(NCENT / 32, DIMC / 32), dim3(32, 8)>>>(C);       // 2
    phi_mma<<<dim3(NB_P, M_TOT / 128), 256, DYN_SMEM>>>(W, bias);       // 3  <- profiled
    feat2_k<<<M_TOT / 256, 256>>>();                                    // 4
    cnorm2_k<<<NCENT / 8, 256>>>();                                     // 5
    dist_mma<<<dim3(NB_D, M_TOT / 128), 256, DYN_SMEM>>>();             // 6
    topk_kernel<<<M_TOT / 4, 128>>>(r, out);                            // 7
    loss_kernel<<<1, 256>>>(out);                                       // 8
}

// round 13
// speedup vs baseline: 1.0004x; 1.0004x over previous
#include <cuda_runtime.h>
#include <cuda_bf16.h>
#include <math.h>
#include <stdint.h>

#define DIMC   1792
#define M_TOT  16384        // 4 * 64 * 64
#define NCENT  4096
#define HW     4096
#define NB_D   32           // dist n-tiles of 128
#define NB_P   14           // phi  n-tiles of 128
#define KSTEPS 28           // 1792 / 64

// ---------------- scratch ---------------------------------------------------
__device__ __align__(1024) __nv_bfloat16 g_sample_t[(size_t)M_TOT * DIMC];
__device__ __align__(1024) __nv_bfloat16 g_phi_bf[(size_t)M_TOT * DIMC];
__device__ __align__(1024) __nv_bfloat16 g_Ct[(size_t)NCENT * DIMC];
__device__ __align__(1024) __nv_bfloat16 g_Wbf[(size_t)DIMC * DIMC];
__device__ float g_feat2p[M_TOT * NB_P];
__device__ float g_feat2[M_TOT];
__device__ float g_cnorm[NCENT];
__device__ float g_cand[(size_t)M_TOT * NB_D * 6];
__device__ float g_losspart[M_TOT];

// ---------------- helpers ----------------------------------------------------
__device__ __forceinline__ uint32_t smem_u32(const void* p) {
    uint32_t a;
    asm("{ .reg .u64 t; cvta.to.shared.u64 t, %1; cvt.u32.u64 %0, t; }" : "=r"(a) : "l"(p));
    return a;
}
__device__ __forceinline__ void cp16(uint32_t dst, const void* src) {
    asm volatile("cp.async.cg.shared.global [%0], [%1], 16;" :: "r"(dst), "l"(src));
}
__device__ __forceinline__ void insert6(float (&t)[6], float v) {
    if (v < t[5]) {
        t[5] = v;
        #pragma unroll
        for (int j = 5; j > 0; --j)
            if (t[j] < t[j-1]) { float tmp = t[j-1]; t[j-1] = t[j]; t[j] = tmp; }
    }
}

// stage: A(128 rows x 128B) + B(128 rows x 128B) = 32KB; 3 stages = 96KB
#define STG_BYTES 32768
#define B_OFF     16384
#define DYN_SMEM  (3 * STG_BYTES)
// full SW128 swizzle: row r (0..127, 128B pitch), 16B-chunk c (0..7)
__device__ __forceinline__ uint32_t swz(int r, int c) {
    return (uint32_t)(r * 128 + ((c ^ (r & 7)) * 16));
}

__device__ __forceinline__ void load_stage(uint32_t sb, int s,
                                           const __nv_bfloat16* A,
                                           const __nv_bfloat16* B,
                                           int k0, int tid) {
    uint32_t abase = sb + s * STG_BYTES;
    uint32_t bbase = abase + B_OFF;
    #pragma unroll
    for (int i = 0; i < 4; ++i) {           // A: 128 rows x 128B
        int slot = tid + i * 256;
        int r = slot >> 3, c = slot & 7;
        cp16(abase + swz(r, c), (const char*)A + ((size_t)r * DIMC + k0 + c * 8) * 2);
    }
    #pragma unroll
    for (int i = 0; i < 4; ++i) {           // B: 128 rows x 128B
        int slot = tid + i * 256;
        int r = slot >> 3, c = slot & 7;
        cp16(bbase + swz(r, c), (const char*)B + ((size_t)r * DIMC + k0 + c * 8) * 2);
    }
    asm volatile("cp.async.commit_group;" ::: "memory");
}

#define MMA_BF16(ac, a, b0, b1) \
    asm volatile( \
        "mma.sync.aligned.m16n8k16.row.col.f32.bf16.bf16.f32 " \
        "{%0,%1,%2,%3}, {%4,%5,%6,%7}, {%8,%9}, {%0,%1,%2,%3};" \
        : "+f"((ac)[0]), "+f"((ac)[1]), "+f"((ac)[2]), "+f"((ac)[3]) \
        : "r"((a)[0]), "r"((a)[1]), "r"((a)[2]), "r"((a)[3]), \
          "r"(b0), "r"(b1))

#define LDSM_A(dst, addr) \
    asm volatile("ldmatrix.sync.aligned.m8n8.x4.shared.b16 {%0,%1,%2,%3}, [%4];" \
                 : "=r"((dst)[0]), "=r"((dst)[1]), "=r"((dst)[2]), "=r"((dst)[3]) \
                 : "r"(addr))

// ---------------- main GEMM: 128x128 tile, 8 warps (32x64 each), K=1792 ------
// kt0: K-loop rotation (in kt units) to anti-phase co-resident CTAs.
__device__ __forceinline__ void gemm_main(const __nv_bfloat16* A,
                                          const __nv_bfloat16* B,
                                          uint32_t sb, int kt0,
                                          float (&acc)[2][8][4]) {
    int tid = threadIdx.x, lane = tid & 31, w = tid >> 5;
    int wm = w & 3, wn = w >> 2;

    int kk0 = kt0;
    int kk1 = kt0 + 1; if (kk1 >= KSTEPS) kk1 -= KSTEPS;
    load_stage(sb, 0, A, B, kk0 * 64, tid);
    load_stage(sb, 1, A, B, kk1 * 64, tid);
    asm volatile("cp.async.wait_group 1;" ::: "memory");
    __syncthreads();

    for (int kt = 0; kt < KSTEPS; ++kt) {
        int s = kt % 3;
        if (kt + 2 < KSTEPS) {
            int kk2 = kt + 2 + kt0; if (kk2 >= KSTEPS) kk2 -= KSTEPS;
            load_stage(sb, (kt + 2) % 3, A, B, kk2 * 64, tid);
        } else {
            asm volatile("cp.async.commit_group;" ::: "memory");
        }

        uint32_t abase = sb + s * STG_BYTES;
        uint32_t bbase = abase + B_OFF;

        uint32_t afr[2][2][4];   // [buf][mi][4]
        // prime A for ks=0
        #pragma unroll
        for (int mi = 0; mi < 2; ++mi) {
            int r = wm * 32 + mi * 16 + (lane & 15);
            int c = (lane >> 4);
            LDSM_A(afr[0][mi], abase + swz(r, c));
        }

        #pragma unroll
        for (int ks = 0; ks < 4; ++ks) {
            int cur = ks & 1;
            // prefetch A for ks+1 — flies under this ks's B loads + MMAs
            if (ks < 3) {
                #pragma unroll
                for (int mi = 0; mi < 2; ++mi) {
                    int r = wm * 32 + mi * 16 + (lane & 15);
                    int c = (ks + 1) * 2 + (lane >> 4);
                    LDSM_A(afr[cur ^ 1][mi], abase + swz(r, c));
                }
            }
            // interleaved B loads + dependent MMAs
            #pragma unroll
            for (int nq = 0; nq < 4; ++nq) {
                uint32_t b00, b01, b10, b11;
                int q = lane >> 3;
                int r = wn * 64 + nq * 16 + (q >> 1) * 8 + (lane & 7);
                int c = ks * 2 + (q & 1);
                uint32_t addr = bbase + swz(r, c);
                asm volatile("ldmatrix.sync.aligned.m8n8.x4.shared.b16 {%0,%1,%2,%3}, [%4];"
                             : "=r"(b00), "=r"(b01), "=r"(b10), "=r"(b11)
                             : "r"(addr));
                MMA_BF16(acc[0][nq * 2],     afr[cur][0], b00, b01);
                MMA_BF16(acc[1][nq * 2],     afr[cur][1], b00, b01);
                MMA_BF16(acc[0][nq * 2 + 1], afr[cur][0], b10, b11);
                MMA_BF16(acc[1][nq * 2 + 1], afr[cur][1], b10, b11);
            }
        }
        asm volatile("cp.async.wait_group 1;" ::: "memory");
        __syncthreads();
    }
}

// ---------------- prepass kernels --------------------------------------------
__global__ void convert_W(const float* __restrict__ W) {
    int o = blockIdx.x;
    for (int c = threadIdx.x; c < DIMC; c += 256)
        g_Wbf[(size_t)o * DIMC + c] = __float2bfloat16(W[(size_t)o * 1794 + c]);
}

// tile: 32 hw x 64 c; smem [hw][c] padded; bf16x2 vectorized stores (128B/warp)
__global__ void transpose_sample(const float* __restrict__ S) {
    __shared__ float t[32][65];
    int b = blockIdx.z;
    int hw0 = blockIdx.x * 32, c0 = blockIdx.y * 64;
    int tx = threadIdx.x, ty = threadIdx.y;   // (32, 8)
    const float* src = S + ((size_t)b * DIMC + c0) * HW + hw0;
    #pragma unroll
    for (int i = 0; i < 8; ++i) {
        int cr = ty + i * 8;
        t[tx][cr] = src[(size_t)cr * HW + tx];
    }
    __syncthreads();
    __nv_bfloat16* dst = g_sample_t + ((size_t)b * HW + hw0) * DIMC + c0;
    #pragma unroll
    for (int i = 0; i < 4; ++i) {
        int hw = ty + i * 8;
        __nv_bfloat162 v = __floats2bfloat162_rn(t[hw][tx * 2], t[hw][tx * 2 + 1]);
        *(__nv_bfloat162*)&dst[(size_t)hw * DIMC + tx * 2] = v;
    }
}

__global__ void transpose_C(const float* __restrict__ C) {
    __shared__ float t[32][33];
    int k0 = blockIdx.x * 32, c0 = blockIdx.y * 32;
    int tx = threadIdx.x, ty = threadIdx.y;
    #pragma unroll
    for (int i = 0; i < 4; ++i)
        t[ty + i * 8][tx] = C[(size_t)(c0 + ty + i * 8) * NCENT + k0 + tx];
    __syncthreads();
    #pragma unroll
    for (int i = 0; i < 4; ++i)
        g_Ct[(size_t)(k0 + ty + i * 8) * DIMC + c0 + tx] = __float2bfloat16(t[tx][ty + i * 8]);
}

// warp-per-center, uint4 loads
__global__ void cnorm2_k() {
    int w = threadIdx.x >> 5, lane = threadIdx.x & 31;
    int k = blockIdx.x * 8 + w;
    const uint4* row = (const uint4*)(g_Ct + (size_t)k * DIMC);
    float s = 0.f;
    for (int i = lane; i < 224; i += 32) {
        uint4 v = row[i];
        const __nv_bfloat162* h = (const __nv_bfloat162*)&v;
        #pragma unroll
        for (int j = 0; j < 4; ++j) {
            float2 f = __bfloat1622float2(h[j]);
            s += f.x * f.x + f.y * f.y;
        }
    }
    #pragma unroll
    for (int o = 16; o; o >>= 1) s += __shfl_xor_sync(0xffffffffu, s, o);
    if (lane == 0) g_cnorm[k] = s;
}

// ---------------- phi GEMM (coordconv 1x1) ------------------------------------
__global__ __launch_bounds__(256, 2) void phi_mma(const float* __restrict__ W,
                                                  const float* __restrict__ bias) {
    extern __shared__ __align__(1024) unsigned char smem[];
    uint32_t sb = smem_u32(smem);
    const int n0 = blockIdx.x * 128;
    const int p0 = blockIdx.y * 128;
    int bid = blockIdx.y * gridDim.x + blockIdx.x;
    int kt0 = ((bid / 148) & 1) * (KSTEPS / 2);

    float acc[2][8][4] = {};
    gemm_main(g_sample_t + (size_t)p0 * DIMC, g_Wbf + (size_t)n0 * DIMC, sb, kt0, acc);

    int tid = threadIdx.x, lane = tid & 31, w = tid >> 5;
    int wm = w & 3, wn = w >> 2, gid = lane >> 2, tq = lane & 3;

    // stage coord weights + bias in smem
    float* smw = (float*)smem;            // [128]wx [128]wy [128]b
    float* smf = (float*)(smem + 2048);   // [128][2]
    if (tid < 128) {
        size_t col = (size_t)(n0 + tid);
        smw[tid]       = __ldg(&W[col * 1794 + 1792]);
        smw[128 + tid] = __ldg(&W[col * 1794 + 1793]);
        smw[256 + tid] = __ldg(&bias[col]);
    }
    __syncthreads();

    #pragma unroll
    for (int mi = 0; mi < 2; ++mi)
        #pragma unroll
        for (int hh = 0; hh < 2; ++hh) {
            int row = wm * 32 + mi * 16 + hh * 8 + gid;
            int p = p0 + row;
            int hw = p & 4095;
            float xx = -1.f + 2.f * (float)(hw & 63) * (1.f / 63.f);
            float yy = -1.f + 2.f * (float)(hw >> 6) * (1.f / 63.f);
            float sq = 0.f;
            #pragma unroll
            for (int ni = 0; ni < 8; ++ni) {
                int ci = wn * 64 + ni * 8 + tq * 2;
                float v0 = acc[mi][ni][hh * 2]     + xx * smw[ci]   + yy * smw[128 + ci]   + smw[256 + ci];
                float v1 = acc[mi][ni][hh * 2 + 1] + xx * smw[ci+1] + yy * smw[128 + ci+1] + smw[256 + ci+1];
                __nv_bfloat162 bb = __floats2bfloat162_rn(v0, v1);
                *(uint32_t*)&g_phi_bf[(size_t)p * DIMC + n0 + ci] = *(uint32_t*)&bb;
                float f0 = __bfloat162float(bb.x), f1 = __bfloat162float(bb.y);
                sq += f0 * f0 + f1 * f1;
            }
            sq += __shfl_xor_sync(0xffffffffu, sq, 1);
            sq += __shfl_xor_sync(0xffffffffu, sq, 2);
            if (tq == 0) smf[row * 2 + wn] = sq;
        }
    __syncthreads();
    if (tid < 128)
        g_feat2p[(size_t)(p0 + tid) * NB_P + blockIdx.x] = smf[tid * 2] + smf[tid * 2 + 1];
}

__global__ void feat2_k() {
    int p = blockIdx.x * 256 + threadIdx.x;
    float s = 0.f;
    #pragma unroll
    for (int i = 0; i < NB_P; ++i) s += g_feat2p[(size_t)p * NB_P + i];
    g_feat2[p] = s;
}

// ---------------- dist GEMM + per-tile top-6 ----------------------------------
__global__ __launch_bounds__(256, 2) void dist_mma() {
    extern __shared__ __align__(1024) unsigned char smem[];
    uint32_t sb = smem_u32(smem);
    const int nb = blockIdx.x;
    const int n0 = nb * 128;
    const int p0 = blockIdx.y * 128;
    int bid = blockIdx.y * gridDim.x + blockIdx.x;
    int kt0 = ((bid / 148) & 1) * (KSTEPS / 2);

    float acc[2][8][4] = {};
    gemm_main(g_phi_bf + (size_t)p0 * DIMC, g_Ct + (size_t)n0 * DIMC, sb, kt0, acc);

    int tid = threadIdx.x, lane = tid & 31, w = tid >> 5;
    int wm = w & 3, wn = w >> 2, gid = lane >> 2, tq = lane & 3;

    // hoist per-row feat2 into registers before smem staging
    float f2r[2][2];
    #pragma unroll
    for (int mi = 0; mi < 2; ++mi)
        #pragma unroll
        for (int hh = 0; hh < 2; ++hh)
            f2r[mi][hh] = g_feat2[p0 + wm * 32 + mi * 16 + hh * 8 + gid];

    float* smc = (float*)smem;                 // [128] cnorm
    float* sm_t6 = (float*)(smem + 1024);      // [128][2][6]
    if (tid < 128) smc[tid] = g_cnorm[n0 + tid];
    __syncthreads();

    #pragma unroll
    for (int mi = 0; mi < 2; ++mi)
        #pragma unroll
        for (int hh = 0; hh < 2; ++hh) {
            int row = wm * 32 + mi * 16 + hh * 8 + gid;
            float f2 = f2r[mi][hh];
            float t6[6];
            #pragma unroll
            for (int j = 0; j < 6; ++j) t6[j] = 3.4e38f;
            #pragma unroll
            for (int ni = 0; ni < 8; ++ni) {
                int ci = wn * 64 + ni * 8 + tq * 2;
                insert6(t6, f2 + smc[ci]     - 2.f * acc[mi][ni][hh * 2]);
                insert6(t6, f2 + smc[ci + 1] - 2.f * acc[mi][ni][hh * 2 + 1]);
            }
            #pragma unroll
            for (int off = 1; off <= 2; off <<= 1) {
                float o6[6];
                #pragma unroll
                for (int j = 0; j < 6; ++j) o6[j] = __shfl_xor_sync(0xffffffffu, t6[j], off);
                #pragma unroll
                for (int j = 0; j < 6; ++j) insert6(t6, o6[j]);
            }
            if (tq == 0) {
                #pragma unroll
                for (int j = 0; j < 6; ++j) sm_t6[(row * 2 + wn) * 6 + j] = t6[j];
            }
        }
    __syncthreads();
    if (tid < 128) {
        float t6[6];
        #pragma unroll
        for (int j = 0; j < 6; ++j) t6[j] = 3.4e38f;
        #pragma unroll
        for (int v = 0; v < 12; ++v) insert6(t6, sm_t6[tid * 12 + v]);
        size_t base = ((size_t)(p0 + tid) * NB_D + nb) * 6;
        #pragma unroll
        for (int j = 0; j < 6; ++j) g_cand[base + j] = t6[j];
    }
}

// ---------------- topk merge + score + loss -----------------------------------
__global__ void topk_kernel(const float* __restrict__ r_in, float* __restrict__ out) {
    int warp = threadIdx.x >> 5;
    int lane = threadIdx.x & 31;
    int p = blockIdx.x * 4 + warp;
    const float* cand = g_cand + (size_t)p * (NB_D * 6);   // 192 values

    float t6[6];
    #pragma unroll
    for (int j = 0; j < 6; ++j) t6[j] = 3.4e38f;
    #pragma unroll
    for (int j = 0; j < 6; ++j) insert6(t6, cand[lane + 32 * j]);

    #pragma unroll
    for (int off = 16; off > 0; off >>= 1) {
        float o6[6];
        #pragma unroll
        for (int j = 0; j < 6; ++j) o6[j] = __shfl_xor_sync(0xffffffffu, t6[j], off);
        #pragma unroll
        for (int j = 0; j < 6; ++j) insert6(t6, o6[j]);
    }

    if (lane == 0) {
        float rr = r_in[0];
        float r2 = rr * rr;
        float d0 = sqrtf(fmaxf(t6[0], 0.f));
        float d1 = sqrtf(fmaxf(t6[1], 0.f));
        float d2 = sqrtf(fmaxf(t6[2], 0.f));
        float w0 = 1.f / (1.f + expf(d0 - d1) + expf(d0 - d2));
        out[1 + p] = w0 * d0;

        float att = fmaxf(t6[0] - r2, 0.f) + fmaxf(t6[1] - r2, 0.f) + fmaxf(t6[2] - r2, 0.f);
        float rep = fmaxf(r2 - t6[3] - 0.1f, 0.f) + fmaxf(r2 - t6[4] - 0.1f, 0.f)
                  + fmaxf(r2 - t6[5] - 0.1f, 0.f);
        g_losspart[p] = att + rep;
    }
}

__global__ void loss_kernel(float* __restrict__ out) {
    __shared__ float sbuf[256];
    float s = 0.f;
    for (int i = threadIdx.x; i < M_TOT; i += 256) s += g_losspart[i];
    sbuf[threadIdx.x] = s;
    __syncthreads();
    for (int o = 128; o > 0; o >>= 1) {
        if (threadIdx.x < o) sbuf[threadIdx.x] += sbuf[threadIdx.x + o];
        __syncthreads();
    }
    if (threadIdx.x == 0)
        out[0] = sbuf[0] * (1000.f / (float)(M_TOT * 3));
}

// ---------------- launcher ------------------------------------------------------
extern "C" void kernel_launch(void* const* d_in, const int* in_sizes, int n_in,
                              void* d_out, int out_size) {
    const float* sample = (const float*)d_in[0];
    const float* W      = (const float*)d_in[1];
    const float* bias   = (const float*)d_in[2];
    const float* C      = (const float*)d_in[3];
    const float* r      = (const float*)d_in[4];
    float* out = (float*)d_out;

    cudaFuncSetAttribute(phi_mma, cudaFuncAttributeMaxDynamicSharedMemorySize, DYN_SMEM);
    cudaFuncSetAttribute(dist_mma, cudaFuncAttributeMaxDynamicSharedMemorySize, DYN_SMEM);

    // phi_mma stays at launch index 3 (the ncu sampling slot)
    convert_W<<<DIMC, 256>>>(W);                                        // 0
    transpose_sample<<<dim3(HW / 32, DIMC / 64, 4), dim3(32, 8)>>>(sample); // 1
    transpose_C<<<dim3(NCENT / 32, DIMC / 32), dim3(32, 8)>>>(C);       // 2
    phi_mma<<<dim3(NB_P, M_TOT / 128), 256, DYN_SMEM>>>(W, bias);       // 3  <- profiled
    feat2_k<<<M_TOT / 256, 256>>>();                                    // 4
    cnorm2_k<<<NCENT / 8, 256>>>();                                     // 5
    dist_mma<<<dim3(NB_D, M_TOT / 128), 256, DYN_SMEM>>>();             // 6
    topk_kernel<<<M_TOT / 4, 128>>>(r, out);                            // 7
    loss_kernel<<<1, 256>>>(out);                                       // 8
}

// round 14
// speedup vs baseline: 1.0023x; 1.0019x over previous
#include <cuda_runtime.h>
#include <cuda_bf16.h>
#include <math.h>
#include <stdint.h>

#define DIMC   1792
#define M_TOT  16384        // 4 * 64 * 64
#define NCENT  4096
#define HW     4096
#define NB_D   32           // dist n-tiles of 128
#define NB_P   14           // phi  n-tiles of 128
#define KSTEPS 28           // 1792 / 64

// ---------------- scratch ---------------------------------------------------
__device__ __align__(1024) __nv_bfloat16 g_sample_t[(size_t)M_TOT * DIMC];
__device__ __align__(1024) __nv_bfloat16 g_phi_bf[(size_t)M_TOT * DIMC];
__device__ __align__(1024) __nv_bfloat16 g_Ct[(size_t)NCENT * DIMC];
__device__ __align__(1024) __nv_bfloat16 g_Wbf[(size_t)DIMC * DIMC];
__device__ float g_feat2p[M_TOT * NB_P];
__device__ float g_feat2[M_TOT];
__device__ float g_cnorm[NCENT];
__device__ float g_cand[(size_t)M_TOT * NB_D * 6];
__device__ float g_losspart[M_TOT];

// ---------------- helpers ----------------------------------------------------
__device__ __forceinline__ uint32_t smem_u32(const void* p) {
    uint32_t a;
    asm("{ .reg .u64 t; cvta.to.shared.u64 t, %1; cvt.u32.u64 %0, t; }" : "=r"(a) : "l"(p));
    return a;
}
__device__ __forceinline__ void cp16(uint32_t dst, const void* src) {
    asm volatile("cp.async.cg.shared.global [%0], [%1], 16;" :: "r"(dst), "l"(src));
}
__device__ __forceinline__ void insert6(float (&t)[6], float v) {
    if (v < t[5]) {
        t[5] = v;
        #pragma unroll
        for (int j = 5; j > 0; --j)
            if (t[j] < t[j-1]) { float tmp = t[j-1]; t[j-1] = t[j]; t[j] = tmp; }
    }
}

// stage: A(128 rows x 128B) + B(128 rows x 128B) = 32KB; 3 stages = 96KB
#define STG_BYTES 32768
#define B_OFF     16384
#define DYN_SMEM  (3 * STG_BYTES)
// full SW128 swizzle: row r (0..127, 128B pitch), 16B-chunk c (0..7)
__device__ __forceinline__ uint32_t swz(int r, int c) {
    return (uint32_t)(r * 128 + ((c ^ (r & 7)) * 16));
}

__device__ __forceinline__ void load_stage(uint32_t sb, int s,
                                           const __nv_bfloat16* A,
                                           const __nv_bfloat16* B,
                                           int k0, int tid) {
    uint32_t abase = sb + s * STG_BYTES;
    uint32_t bbase = abase + B_OFF;
    #pragma unroll
    for (int i = 0; i < 4; ++i) {           // A: 128 rows x 128B
        int slot = tid + i * 256;
        int r = slot >> 3, c = slot & 7;
        cp16(abase + swz(r, c), (const char*)A + ((size_t)r * DIMC + k0 + c * 8) * 2);
    }
    #pragma unroll
    for (int i = 0; i < 4; ++i) {           // B: 128 rows x 128B
        int slot = tid + i * 256;
        int r = slot >> 3, c = slot & 7;
        cp16(bbase + swz(r, c), (const char*)B + ((size_t)r * DIMC + k0 + c * 8) * 2);
    }
    asm volatile("cp.async.commit_group;" ::: "memory");
}

#define MMA_BF16(ac, a, b0, b1) \
    asm volatile( \
        "mma.sync.aligned.m16n8k16.row.col.f32.bf16.bf16.f32 " \
        "{%0,%1,%2,%3}, {%4,%5,%6,%7}, {%8,%9}, {%0,%1,%2,%3};" \
        : "+f"((ac)[0]), "+f"((ac)[1]), "+f"((ac)[2]), "+f"((ac)[3]) \
        : "r"((a)[0]), "r"((a)[1]), "r"((a)[2]), "r"((a)[3]), \
          "r"(b0), "r"(b1))

#define LDSM_A(dst, addr) \
    asm volatile("ldmatrix.sync.aligned.m8n8.x4.shared.b16 {%0,%1,%2,%3}, [%4];" \
                 : "=r"((dst)[0]), "=r"((dst)[1]), "=r"((dst)[2]), "=r"((dst)[3]) \
                 : "r"(addr))

// ---------------- main GEMM: 128x128 tile, 8 warps (32x64 each), K=1792 ------
// A fragments software-pipelined across ks (double-buffered, indexed ks&1).
__device__ __forceinline__ void gemm_main(const __nv_bfloat16* A,
                                          const __nv_bfloat16* B,
                                          uint32_t sb,
                                          float (&acc)[2][8][4]) {
    int tid = threadIdx.x, lane = tid & 31, w = tid >> 5;
    int wm = w & 3, wn = w >> 2;

    load_stage(sb, 0, A, B, 0, tid);
    load_stage(sb, 1, A, B, 64, tid);
    asm volatile("cp.async.wait_group 1;" ::: "memory");
    __syncthreads();

    for (int kt = 0; kt < KSTEPS; ++kt) {
        int s = kt % 3;
        if (kt + 2 < KSTEPS)
            load_stage(sb, (kt + 2) % 3, A, B, (kt + 2) * 64, tid);
        else
            asm volatile("cp.async.commit_group;" ::: "memory");

        uint32_t abase = sb + s * STG_BYTES;
        uint32_t bbase = abase + B_OFF;

        uint32_t afr[2][2][4];   // [buf][mi][4]
        #pragma unroll
        for (int mi = 0; mi < 2; ++mi) {
            int r = wm * 32 + mi * 16 + (lane & 15);
            int c = (lane >> 4);
            LDSM_A(afr[0][mi], abase + swz(r, c));
        }

        #pragma unroll
        for (int ks = 0; ks < 4; ++ks) {
            int cur = ks & 1;
            if (ks < 3) {
                #pragma unroll
                for (int mi = 0; mi < 2; ++mi) {
                    int r = wm * 32 + mi * 16 + (lane & 15);
                    int c = (ks + 1) * 2 + (lane >> 4);
                    LDSM_A(afr[cur ^ 1][mi], abase + swz(r, c));
                }
            }
            #pragma unroll
            for (int nq = 0; nq < 4; ++nq) {
                uint32_t b00, b01, b10, b11;
                int q = lane >> 3;
                int r = wn * 64 + nq * 16 + (q >> 1) * 8 + (lane & 7);
                int c = ks * 2 + (q & 1);
                uint32_t addr = bbase + swz(r, c);
                asm volatile("ldmatrix.sync.aligned.m8n8.x4.shared.b16 {%0,%1,%2,%3}, [%4];"
                             : "=r"(b00), "=r"(b01), "=r"(b10), "=r"(b11)
                             : "r"(addr));
                MMA_BF16(acc[0][nq * 2],     afr[cur][0], b00, b01);
                MMA_BF16(acc[1][nq * 2],     afr[cur][1], b00, b01);
                MMA_BF16(acc[0][nq * 2 + 1], afr[cur][0], b10, b11);
                MMA_BF16(acc[1][nq * 2 + 1], afr[cur][1], b10, b11);
            }
        }
        asm volatile("cp.async.wait_group 1;" ::: "memory");
        __syncthreads();
    }
}

// ---------------- fused prepass: all independent prep work in ONE launch -------
// block partition:
//   [0, 14336)            transpose_sample  (128 x 28 x 4 tiles)
//   [14336, 21504)        transpose_C       (128 x 56 tiles)
//   [21504, 23296)        convert_W         (1792 rows)
//   [23296, 23424)        cnorm from C      (128 blocks x 32 centers)
#define NB_TS  14336
#define NB_TC  7168
#define NB_CW  1792
#define NB_CN  128
#define NB_PREP (NB_TS + NB_TC + NB_CW + NB_CN)

__global__ void prep_fused(const float* __restrict__ S,
                           const float* __restrict__ W,
                           const float* __restrict__ C) {
    __shared__ float t[32][65];
    int idx = blockIdx.x;
    int tid = threadIdx.x;

    if (idx < NB_TS) {
        // ---- transpose_sample: tile 32 hw x 64 c ----
        int bz = idx / 3584;
        int r = idx - bz * 3584;
        int bx = r & 127, by = r >> 7;
        int hw0 = bx * 32, c0 = by * 64;
        int tx = tid & 31, ty = tid >> 5;
        const float* src = S + ((size_t)bz * DIMC + c0) * HW + hw0;
        #pragma unroll
        for (int i = 0; i < 8; ++i) {
            int cr = ty + i * 8;
            t[tx][cr] = src[(size_t)cr * HW + tx];
        }
        __syncthreads();
        __nv_bfloat16* dst = g_sample_t + ((size_t)bz * HW + hw0) * DIMC + c0;
        #pragma unroll
        for (int i = 0; i < 4; ++i) {
            int hw = ty + i * 8;
            __nv_bfloat162 v = __floats2bfloat162_rn(t[hw][tx * 2], t[hw][tx * 2 + 1]);
            *(__nv_bfloat162*)&dst[(size_t)hw * DIMC + tx * 2] = v;
        }
    } else if (idx < NB_TS + NB_TC) {
        // ---- transpose_C: tile 32 k x 32 c ----
        int j = idx - NB_TS;
        int k0 = (j & 127) * 32, c0 = (j >> 7) * 32;
        int tx = tid & 31, ty = tid >> 5;
        #pragma unroll
        for (int i = 0; i < 4; ++i)
            t[ty + i * 8][tx] = C[(size_t)(c0 + ty + i * 8) * NCENT + k0 + tx];
        __syncthreads();
        #pragma unroll
        for (int i = 0; i < 4; ++i)
            g_Ct[(size_t)(k0 + ty + i * 8) * DIMC + c0 + tx] =
                __float2bfloat16(t[tx][ty + i * 8]);
    } else if (idx < NB_TS + NB_TC + NB_CW) {
        // ---- convert_W ----
        int o = idx - (NB_TS + NB_TC);
        for (int c = tid; c < DIMC; c += 256)
            g_Wbf[(size_t)o * DIMC + c] = __float2bfloat16(W[(size_t)o * 1794 + c]);
    } else {
        // ---- cnorm: 32 centers per block, 8-way c split, bf16-rounded ----
        int b = idx - (NB_TS + NB_TC + NB_CW);
        int k = b * 32 + (tid & 31);
        int ch = tid >> 5;                     // 0..7, 224 c's each
        float s = 0.f;
        int cbeg = ch * 224;
        for (int c = cbeg; c < cbeg + 224; ++c) {
            float v = __bfloat162float(__float2bfloat16(C[(size_t)c * NCENT + k]));
            s += v * v;
        }
        float* red = &t[0][0];                 // [32 k][8 ch]
        red[(tid & 31) * 8 + ch] = s;
        __syncthreads();
        if (tid < 32) {
            float a = 0.f;
            #pragma unroll
            for (int j2 = 0; j2 < 8; ++j2) a += red[tid * 8 + j2];
            g_cnorm[b * 32 + tid] = a;
        }
    }
}

// ---------------- phi GEMM (coordconv 1x1) ------------------------------------
__global__ __launch_bounds__(256, 2) void phi_mma(const float* __restrict__ W,
                                                  const float* __restrict__ bias) {
    extern __shared__ __align__(1024) unsigned char smem[];
    uint32_t sb = smem_u32(smem);
    const int n0 = blockIdx.x * 128;
    const int p0 = blockIdx.y * 128;

    float acc[2][8][4] = {};
    gemm_main(g_sample_t + (size_t)p0 * DIMC, g_Wbf + (size_t)n0 * DIMC, sb, acc);

    int tid = threadIdx.x, lane = tid & 31, w = tid >> 5;
    int wm = w & 3, wn = w >> 2, gid = lane >> 2, tq = lane & 3;

    float* smw = (float*)smem;            // [128]wx [128]wy [128]b
    float* smf = (float*)(smem + 2048);   // [128][2]
    if (tid < 128) {
        size_t col = (size_t)(n0 + tid);
        smw[tid]       = __ldg(&W[col * 1794 + 1792]);
        smw[128 + tid] = __ldg(&W[col * 1794 + 1793]);
        smw[256 + tid] = __ldg(&bias[col]);
    }
    __syncthreads();

    #pragma unroll
    for (int mi = 0; mi < 2; ++mi)
        #pragma unroll
        for (int hh = 0; hh < 2; ++hh) {
            int row = wm * 32 + mi * 16 + hh * 8 + gid;
            int p = p0 + row;
            int hw = p & 4095;
            float xx = -1.f + 2.f * (float)(hw & 63) * (1.f / 63.f);
            float yy = -1.f + 2.f * (float)(hw >> 6) * (1.f / 63.f);
            float sq = 0.f;
            #pragma unroll
            for (int ni = 0; ni < 8; ++ni) {
                int ci = wn * 64 + ni * 8 + tq * 2;
                float v0 = acc[mi][ni][hh * 2]     + xx * smw[ci]   + yy * smw[128 + ci]   + smw[256 + ci];
                float v1 = acc[mi][ni][hh * 2 + 1] + xx * smw[ci+1] + yy * smw[128 + ci+1] + smw[256 + ci+1];
                __nv_bfloat162 bb = __floats2bfloat162_rn(v0, v1);
                *(uint32_t*)&g_phi_bf[(size_t)p * DIMC + n0 + ci] = *(uint32_t*)&bb;
                float f0 = __bfloat162float(bb.x), f1 = __bfloat162float(bb.y);
                sq += f0 * f0 + f1 * f1;
            }
            sq += __shfl_xor_sync(0xffffffffu, sq, 1);
            sq += __shfl_xor_sync(0xffffffffu, sq, 2);
            if (tq == 0) smf[row * 2 + wn] = sq;
        }
    __syncthreads();
    if (tid < 128)
        g_feat2p[(size_t)(p0 + tid) * NB_P + blockIdx.x] = smf[tid * 2] + smf[tid * 2 + 1];
}

__global__ void feat2_k() {
    int p = blockIdx.x * 256 + threadIdx.x;
    float s = 0.f;
    #pragma unroll
    for (int i = 0; i < NB_P; ++i) s += g_feat2p[(size_t)p * NB_P + i];
    g_feat2[p] = s;
}

// ---------------- dist GEMM + per-tile top-6 ----------------------------------
__global__ __launch_bounds__(256, 2) void dist_mma() {
    extern __shared__ __align__(1024) unsigned char smem[];
    uint32_t sb = smem_u32(smem);
    const int nb = blockIdx.x;
    const int n0 = nb * 128;
    const int p0 = blockIdx.y * 128;

    float acc[2][8][4] = {};
    gemm_main(g_phi_bf + (size_t)p0 * DIMC, g_Ct + (size_t)n0 * DIMC, sb, acc);

    int tid = threadIdx.x, lane = tid & 31, w = tid >> 5;
    int wm = w & 3, wn = w >> 2, gid = lane >> 2, tq = lane & 3;

    float f2r[2][2];
    #pragma unroll
    for (int mi = 0; mi < 2; ++mi)
        #pragma unroll
        for (int hh = 0; hh < 2; ++hh)
            f2r[mi][hh] = g_feat2[p0 + wm * 32 + mi * 16 + hh * 8 + gid];

    float* smc = (float*)smem;                 // [128] cnorm
    float* sm_t6 = (float*)(smem + 1024);      // [128][2][6]
    if (tid < 128) smc[tid] = g_cnorm[n0 + tid];
    __syncthreads();

    #pragma unroll
    for (int mi = 0; mi < 2; ++mi)
        #pragma unroll
        for (int hh = 0; hh < 2; ++hh) {
            int row = wm * 32 + mi * 16 + hh * 8 + gid;
            float f2 = f2r[mi][hh];
            float t6[6];
            #pragma unroll
            for (int j = 0; j < 6; ++j) t6[j] = 3.4e38f;
            #pragma unroll
            for (int ni = 0; ni < 8; ++ni) {
                int ci = wn * 64 + ni * 8 + tq * 2;
                insert6(t6, f2 + smc[ci]     - 2.f * acc[mi][ni][hh * 2]);
                insert6(t6, f2 + smc[ci + 1] - 2.f * acc[mi][ni][hh * 2 + 1]);
            }
            #pragma unroll
            for (int off = 1; off <= 2; off <<= 1) {
                float o6[6];
                #pragma unroll
                for (int j = 0; j < 6; ++j) o6[j] = __shfl_xor_sync(0xffffffffu, t6[j], off);
                #pragma unroll
                for (int j = 0; j < 6; ++j) insert6(t6, o6[j]);
            }
            if (tq == 0) {
                #pragma unroll
                for (int j = 0; j < 6; ++j) sm_t6[(row * 2 + wn) * 6 + j] = t6[j];
            }
        }
    __syncthreads();
    if (tid < 128) {
        float t6[6];
        #pragma unroll
        for (int j = 0; j < 6; ++j) t6[j] = 3.4e38f;
        #pragma unroll
        for (int v = 0; v < 12; ++v) insert6(t6, sm_t6[tid * 12 + v]);
        size_t base = ((size_t)(p0 + tid) * NB_D + nb) * 6;
        #pragma unroll
        for (int j = 0; j < 6; ++j) g_cand[base + j] = t6[j];
    }
}

// ---------------- topk merge + score + loss -----------------------------------
__global__ void topk_kernel(const float* __restrict__ r_in, float* __restrict__ out) {
    int warp = threadIdx.x >> 5;
    int lane = threadIdx.x & 31;
    int p = blockIdx.x * 4 + warp;
    const float* cand = g_cand + (size_t)p * (NB_D * 6);   // 192 values

    float t6[6];
    #pragma unroll
    for (int j = 0; j < 6; ++j) t6[j] = 3.4e38f;
    #pragma unroll
    for (int j = 0; j < 6; ++j) insert6(t6, cand[lane + 32 * j]);

    #pragma unroll
    for (int off = 16; off > 0; off >>= 1) {
        float o6[6];
        #pragma unroll
        for (int j = 0; j < 6; ++j) o6[j] = __shfl_xor_sync(0xffffffffu, t6[j], off);
        #pragma unroll
        for (int j = 0; j < 6; ++j) insert6(t6, o6[j]);
    }

    if (lane == 0) {
        float rr = r_in[0];
        float r2 = rr * rr;
        float d0 = sqrtf(fmaxf(t6[0], 0.f));
        float d1 = sqrtf(fmaxf(t6[1], 0.f));
        float d2 = sqrtf(fmaxf(t6[2], 0.f));
        float w0 = 1.f / (1.f + expf(d0 - d1) + expf(d0 - d2));
        out[1 + p] = w0 * d0;

        float att = fmaxf(t6[0] - r2, 0.f) + fmaxf(t6[1] - r2, 0.f) + fmaxf(t6[2] - r2, 0.f);
        float rep = fmaxf(r2 - t6[3] - 0.1f, 0.f) + fmaxf(r2 - t6[4] - 0.1f, 0.f)
                  + fmaxf(r2 - t6[5] - 0.1f, 0.f);
        g_losspart[p] = att + rep;
    }
}

__global__ void loss_kernel(float* __restrict__ out) {
    __shared__ float sbuf[256];
    float s = 0.f;
    for (int i = threadIdx.x; i < M_TOT; i += 256) s += g_losspart[i];
    sbuf[threadIdx.x] = s;
    __syncthreads();
    for (int o = 128; o > 0; o >>= 1) {
        if (threadIdx.x < o) sbuf[threadIdx.x] += sbuf[threadIdx.x + o];
        __syncthreads();
    }
    if (threadIdx.x == 0)
        out[0] = sbuf[0] * (1000.f / (float)(M_TOT * 3));
}

// ---------------- launcher ------------------------------------------------------
extern "C" void kernel_launch(void* const* d_in, const int* in_sizes, int n_in,
                              void* d_out, int out_size) {
    const float* sample = (const float*)d_in[0];
    const float* W      = (const float*)d_in[1];
    const float* bias   = (const float*)d_in[2];
    const float* C      = (const float*)d_in[3];
    const float* r      = (const float*)d_in[4];
    float* out = (float*)d_out;

    cudaFuncSetAttribute(phi_mma, cudaFuncAttributeMaxDynamicSharedMemorySize, DYN_SMEM);
    cudaFuncSetAttribute(dist_mma, cudaFuncAttributeMaxDynamicSharedMemorySize, DYN_SMEM);

    // dist_mma now sits at launch index 3 (the ncu sampling slot)
    prep_fused<<<NB_PREP, 256>>>(sample, W, C);                         // 0
    phi_mma<<<dim3(NB_P, M_TOT / 128), 256, DYN_SMEM>>>(W, bias);       // 1
    feat2_k<<<M_TOT / 256, 256>>>();                                    // 2
    dist_mma<<<dim3(NB_D, M_TOT / 128), 256, DYN_SMEM>>>();             // 3  <- profiled
    topk_kernel<<<M_TOT / 4, 128>>>(r, out);                            // 4
    loss_kernel<<<1, 256>>>(out);                                       // 5
}

// round 15
// speedup vs baseline: 1.0068x; 1.0045x over previous
#include <cuda_runtime.h>
#include <cuda_bf16.h>
#include <math.h>
#include <stdint.h>

#define DIMC   1792
#define M_TOT  16384        // 4 * 64 * 64
#define NCENT  4096
#define HW     4096
#define NB_D   32           // dist n-tiles of 128
#define NB_P   14           // phi  n-tiles of 128
#define KSTEPS 28           // 1792 / 64

// ---------------- scratch ---------------------------------------------------
__device__ __align__(1024) __nv_bfloat16 g_sample_t[(size_t)M_TOT * DIMC];
__device__ __align__(1024) __nv_bfloat16 g_phi_bf[(size_t)M_TOT * DIMC];
__device__ __align__(1024) __nv_bfloat16 g_Ct[(size_t)NCENT * DIMC];
__device__ __align__(1024) __nv_bfloat16 g_Wbf[(size_t)DIMC * DIMC];
__device__ float g_feat2p[M_TOT * NB_P];
__device__ float g_cnorm[NCENT];
__device__ float g_cand[(size_t)M_TOT * NB_D * 6];
__device__ float g_losspart[M_TOT];

// ---------------- helpers ----------------------------------------------------
__device__ __forceinline__ uint32_t smem_u32(const void* p) {
    uint32_t a;
    asm("{ .reg .u64 t; cvta.to.shared.u64 t, %1; cvt.u32.u64 %0, t; }" : "=r"(a) : "l"(p));
    return a;
}
__device__ __forceinline__ void cp16(uint32_t dst, const void* src) {
    asm volatile("cp.async.cg.shared.global [%0], [%1], 16;" :: "r"(dst), "l"(src));
}
__device__ __forceinline__ void insert6(float (&t)[6], float v) {
    if (v < t[5]) {
        t[5] = v;
        #pragma unroll
        for (int j = 5; j > 0; --j)
            if (t[j] < t[j-1]) { float tmp = t[j-1]; t[j-1] = t[j]; t[j] = tmp; }
    }
}

// stage: A(128 rows x 128B) + B(128 rows x 128B) = 32KB; 3 stages = 96KB
#define STG_BYTES 32768
#define B_OFF     16384
#define DYN_SMEM  (3 * STG_BYTES)
// full SW128 swizzle: row r (0..127, 128B pitch), 16B-chunk c (0..7)
__device__ __forceinline__ uint32_t swz(int r, int c) {
    return (uint32_t)(r * 128 + ((c ^ (r & 7)) * 16));
}

__device__ __forceinline__ void load_stage(uint32_t sb, int s,
                                           const __nv_bfloat16* A,
                                           const __nv_bfloat16* B,
                                           int k0, int tid) {
    uint32_t abase = sb + s * STG_BYTES;
    uint32_t bbase = abase + B_OFF;
    #pragma unroll
    for (int i = 0; i < 4; ++i) {           // A: 128 rows x 128B
        int slot = tid + i * 256;
        int r = slot >> 3, c = slot & 7;
        cp16(abase + swz(r, c), (const char*)A + ((size_t)r * DIMC + k0 + c * 8) * 2);
    }
    #pragma unroll
    for (int i = 0; i < 4; ++i) {           // B: 128 rows x 128B
        int slot = tid + i * 256;
        int r = slot >> 3, c = slot & 7;
        cp16(bbase + swz(r, c), (const char*)B + ((size_t)r * DIMC + k0 + c * 8) * 2);
    }
    asm volatile("cp.async.commit_group;" ::: "memory");
}

#define MMA_BF16(ac, a, b0, b1) \
    asm volatile( \
        "mma.sync.aligned.m16n8k16.row.col.f32.bf16.bf16.f32 " \
        "{%0,%1,%2,%3}, {%4,%5,%6,%7}, {%8,%9}, {%0,%1,%2,%3};" \
        : "+f"((ac)[0]), "+f"((ac)[1]), "+f"((ac)[2]), "+f"((ac)[3]) \
        : "r"((a)[0]), "r"((a)[1]), "r"((a)[2]), "r"((a)[3]), \
          "r"(b0), "r"(b1))

#define LDSM4(dst, addr) \
    asm volatile("ldmatrix.sync.aligned.m8n8.x4.shared.b16 {%0,%1,%2,%3}, [%4];" \
                 : "=r"((dst)[0]), "=r"((dst)[1]), "=r"((dst)[2]), "=r"((dst)[3]) \
                 : "r"(addr))

// B LDSM address for (ks, nq)
__device__ __forceinline__ uint32_t b_addr(uint32_t bbase, int wn, int lane,
                                           int ks, int nq) {
    int q = lane >> 3;
    int r = wn * 64 + nq * 16 + (q >> 1) * 8 + (lane & 7);
    int c = ks * 2 + (q & 1);
    return bbase + swz(r, c);
}

// ---------------- main GEMM: 128x128 tile, 8 warps (32x64 each), K=1792 ------
// A fragments double-buffered across ks; B fragments double-buffered across nq
// (with cross-ks tail prefetch) so every MMA group trails its feeding LDSM by
// ~4 MMA groups (~32 cyc) — covering LDS latency.
__device__ __forceinline__ void gemm_main(const __nv_bfloat16* A,
                                          const __nv_bfloat16* B,
                                          uint32_t sb,
                                          float (&acc)[2][8][4]) {
    int tid = threadIdx.x, lane = tid & 31, w = tid >> 5;
    int wm = w & 3, wn = w >> 2;

    load_stage(sb, 0, A, B, 0, tid);
    load_stage(sb, 1, A, B, 64, tid);
    asm volatile("cp.async.wait_group 1;" ::: "memory");
    __syncthreads();

    for (int kt = 0; kt < KSTEPS; ++kt) {
        int s = kt % 3;
        if (kt + 2 < KSTEPS)
            load_stage(sb, (kt + 2) % 3, A, B, (kt + 2) * 64, tid);
        else
            asm volatile("cp.async.commit_group;" ::: "memory");

        uint32_t abase = sb + s * STG_BYTES;
        uint32_t bbase = abase + B_OFF;

        uint32_t afr[2][2][4];   // [buf][mi][4]
        uint32_t bfr[2][4];      // [buf][4]
        // prime A for ks=0
        #pragma unroll
        for (int mi = 0; mi < 2; ++mi) {
            int r = wm * 32 + mi * 16 + (lane & 15);
            int c = (lane >> 4);
            LDSM4(afr[0][mi], abase + swz(r, c));
        }
        // prime B for (ks=0, nq=0)
        LDSM4(bfr[0], b_addr(bbase, wn, lane, 0, 0));

        #pragma unroll
        for (int ks = 0; ks < 4; ++ks) {
            int cur = ks & 1;
            // prefetch A for ks+1
            if (ks < 3) {
                #pragma unroll
                for (int mi = 0; mi < 2; ++mi) {
                    int r = wm * 32 + mi * 16 + (lane & 15);
                    int c = (ks + 1) * 2 + (lane >> 4);
                    LDSM4(afr[cur ^ 1][mi], abase + swz(r, c));
                }
            }
            #pragma unroll
            for (int nq = 0; nq < 4; ++nq) {
                int bb = nq & 1;   // 4 nq per ks -> parity restarts each ks
                // prefetch next B group (next nq, or next ks's nq=0)
                if (nq < 3)
                    LDSM4(bfr[bb ^ 1], b_addr(bbase, wn, lane, ks, nq + 1));
                else if (ks < 3)
                    LDSM4(bfr[bb ^ 1], b_addr(bbase, wn, lane, ks + 1, 0));
                MMA_BF16(acc[0][nq * 2],     afr[cur][0], bfr[bb][0], bfr[bb][1]);
                MMA_BF16(acc[1][nq * 2],     afr[cur][1], bfr[bb][0], bfr[bb][1]);
                MMA_BF16(acc[0][nq * 2 + 1], afr[cur][0], bfr[bb][2], bfr[bb][3]);
                MMA_BF16(acc[1][nq * 2 + 1], afr[cur][1], bfr[bb][2], bfr[bb][3]);
            }
        }
        asm volatile("cp.async.wait_group 1;" ::: "memory");
        __syncthreads();
    }
}

// ---------------- fused prepass -------------------------------------------------
#define NB_TS  14336
#define NB_TC  7168
#define NB_CW  1792
#define NB_CN  128
#define NB_PREP (NB_TS + NB_TC + NB_CW + NB_CN)

__global__ void prep_fused(const float* __restrict__ S,
                           const float* __restrict__ W,
                           const float* __restrict__ C) {
    __shared__ float t[32][65];
    int idx = blockIdx.x;
    int tid = threadIdx.x;

    if (idx < NB_TS) {
        // ---- transpose_sample: tile 32 hw x 64 c ----
        int bz = idx / 3584;
        int r = idx - bz * 3584;
        int bx = r & 127, by = r >> 7;
        int hw0 = bx * 32, c0 = by * 64;
        int tx = tid & 31, ty = tid >> 5;
        const float* src = S + ((size_t)bz * DIMC + c0) * HW + hw0;
        #pragma unroll
        for (int i = 0; i < 8; ++i) {
            int cr = ty + i * 8;
            t[tx][cr] = src[(size_t)cr * HW + tx];
        }
        __syncthreads();
        __nv_bfloat16* dst = g_sample_t + ((size_t)bz * HW + hw0) * DIMC + c0;
        #pragma unroll
        for (int i = 0; i < 4; ++i) {
            int hw = ty + i * 8;
            __nv_bfloat162 v = __floats2bfloat162_rn(t[hw][tx * 2], t[hw][tx * 2 + 1]);
            *(__nv_bfloat162*)&dst[(size_t)hw * DIMC + tx * 2] = v;
        }
    } else if (idx < NB_TS + NB_TC) {
        // ---- transpose_C: tile 32 k x 32 c ----
        int j = idx - NB_TS;
        int k0 = (j & 127) * 32, c0 = (j >> 7) * 32;
        int tx = tid & 31, ty = tid >> 5;
        #pragma unroll
        for (int i = 0; i < 4; ++i)
            t[ty + i * 8][tx] = C[(size_t)(c0 + ty + i * 8) * NCENT + k0 + tx];
        __syncthreads();
        #pragma unroll
        for (int i = 0; i < 4; ++i)
            g_Ct[(size_t)(k0 + ty + i * 8) * DIMC + c0 + tx] =
                __float2bfloat16(t[tx][ty + i * 8]);
    } else if (idx < NB_TS + NB_TC + NB_CW) {
        // ---- convert_W ----
        int o = idx - (NB_TS + NB_TC);
        for (int c = tid; c < DIMC; c += 256)
            g_Wbf[(size_t)o * DIMC + c] = __float2bfloat16(W[(size_t)o * 1794 + c]);
    } else {
        // ---- cnorm: 32 centers per block, 8-way c split, bf16-rounded ----
        int b = idx - (NB_TS + NB_TC + NB_CW);
        int k = b * 32 + (tid & 31);
        int ch = tid >> 5;
        float s = 0.f;
        int cbeg = ch * 224;
        for (int c = cbeg; c < cbeg + 224; ++c) {
            float v = __bfloat162float(__float2bfloat16(C[(size_t)c * NCENT + k]));
            s += v * v;
        }
        float* red = &t[0][0];
        red[(tid & 31) * 8 + ch] = s;
        __syncthreads();
        if (tid < 32) {
            float a = 0.f;
            #pragma unroll
            for (int j2 = 0; j2 < 8; ++j2) a += red[tid * 8 + j2];
            g_cnorm[b * 32 + tid] = a;
        }
    }
}

// ---------------- phi GEMM (coordconv 1x1) ------------------------------------
__global__ __launch_bounds__(256, 2) void phi_mma(const float* __restrict__ W,
                                                  const float* __restrict__ bias) {
    extern __shared__ __align__(1024) unsigned char smem[];
    uint32_t sb = smem_u32(smem);
    const int n0 = blockIdx.x * 128;
    const int p0 = blockIdx.y * 128;

    float acc[2][8][4] = {};
    gemm_main(g_sample_t + (size_t)p0 * DIMC, g_Wbf + (size_t)n0 * DIMC, sb, acc);

    int tid = threadIdx.x, lane = tid & 31, w = tid >> 5;
    int wm = w & 3, wn = w >> 2, gid = lane >> 2, tq = lane & 3;

    float* smw = (float*)smem;            // [128]wx [128]wy [128]b
    float* smf = (float*)(smem + 2048);   // [128][2]
    if (tid < 128) {
        size_t col = (size_t)(n0 + tid);
        smw[tid]       = __ldg(&W[col * 1794 + 1792]);
        smw[128 + tid] = __ldg(&W[col * 1794 + 1793]);
        smw[256 + tid] = __ldg(&bias[col]);
    }
    __syncthreads();

    #pragma unroll
    for (int mi = 0; mi < 2; ++mi)
        #pragma unroll
        for (int hh = 0; hh < 2; ++hh) {
            int row = wm * 32 + mi * 16 + hh * 8 + gid;
            int p = p0 + row;
            int hw = p & 4095;
            float xx = -1.f + 2.f * (float)(hw & 63) * (1.f / 63.f);
            float yy = -1.f + 2.f * (float)(hw >> 6) * (1.f / 63.f);
            float sq = 0.f;
            #pragma unroll
            for (int ni = 0; ni < 8; ++ni) {
                int ci = wn * 64 + ni * 8 + tq * 2;
                float v0 = acc[mi][ni][hh * 2]     + xx * smw[ci]   + yy * smw[128 + ci]   + smw[256 + ci];
                float v1 = acc[mi][ni][hh * 2 + 1] + xx * smw[ci+1] + yy * smw[128 + ci+1] + smw[256 + ci+1];
                __nv_bfloat162 bb = __floats2bfloat162_rn(v0, v1);
                *(uint32_t*)&g_phi_bf[(size_t)p * DIMC + n0 + ci] = *(uint32_t*)&bb;
                float f0 = __bfloat162float(bb.x), f1 = __bfloat162float(bb.y);
                sq += f0 * f0 + f1 * f1;
            }
            sq += __shfl_xor_sync(0xffffffffu, sq, 1);
            sq += __shfl_xor_sync(0xffffffffu, sq, 2);
            if (tq == 0) smf[row * 2 + wn] = sq;
        }
    __syncthreads();
    if (tid < 128)
        g_feat2p[(size_t)(p0 + tid) * NB_P + blockIdx.x] = smf[tid * 2] + smf[tid * 2 + 1];
}

// ---------------- dist GEMM + per-tile top-6 (feat2 folded in) ------------------
__global__ __launch_bounds__(256, 2) void dist_mma() {
    extern __shared__ __align__(1024) unsigned char smem[];
    uint32_t sb = smem_u32(smem);
    const int nb = blockIdx.x;
    const int n0 = nb * 128;
    const int p0 = blockIdx.y * 128;

    float acc[2][8][4] = {};
    gemm_main(g_phi_bf + (size_t)p0 * DIMC, g_Ct + (size_t)n0 * DIMC, sb, acc);

    int tid = threadIdx.x, lane = tid & 31, w = tid >> 5;
    int wm = w & 3, wn = w >> 2, gid = lane >> 2, tq = lane & 3;

    // per-row feat2 = sum of NB_P partials (same order as old feat2_k)
    float f2r[2][2];
    #pragma unroll
    for (int mi = 0; mi < 2; ++mi)
        #pragma unroll
        for (int hh = 0; hh < 2; ++hh) {
            int row = wm * 32 + mi * 16 + hh * 8 + gid;
            const float* fp = &g_feat2p[(size_t)(p0 + row) * NB_P];
            float s = 0.f;
            #pragma unroll
            for (int i = 0; i < NB_P; ++i) s += fp[i];
            f2r[mi][hh] = s;
        }

    float* smc = (float*)smem;                 // [128] cnorm
    float* sm_t6 = (float*)(smem + 1024);      // [128][2][6]
    if (tid < 128) smc[tid] = g_cnorm[n0 + tid];
    __syncthreads();

    #pragma unroll
    for (int mi = 0; mi < 2; ++mi)
        #pragma unroll
        for (int hh = 0; hh < 2; ++hh) {
            int row = wm * 32 + mi * 16 + hh * 8 + gid;
            float f2 = f2r[mi][hh];
            float t6[6];
            #pragma unroll
            for (int j = 0; j < 6; ++j) t6[j] = 3.4e38f;
            #pragma unroll
            for (int ni = 0; ni < 8; ++ni) {
                int ci = wn * 64 + ni * 8 + tq * 2;
                insert6(t6, f2 + smc[ci]     - 2.f * acc[mi][ni][hh * 2]);
                insert6(t6, f2 + smc[ci + 1] - 2.f * acc[mi][ni][hh * 2 + 1]);
            }
            #pragma unroll
            for (int off = 1; off <= 2; off <<= 1) {
                float o6[6];
                #pragma unroll
                for (int j = 0; j < 6; ++j) o6[j] = __shfl_xor_sync(0xffffffffu, t6[j], off);
                #pragma unroll
                for (int j = 0; j < 6; ++j) insert6(t6, o6[j]);
            }
            if (tq == 0) {
                #pragma unroll
                for (int j = 0; j < 6; ++j) sm_t6[(row * 2 + wn) * 6 + j] = t6[j];
            }
        }
    __syncthreads();
    if (tid < 128) {
        float t6[6];
        #pragma unroll
        for (int j = 0; j < 6; ++j) t6[j] = 3.4e38f;
        #pragma unroll
        for (int v = 0; v < 12; ++v) insert6(t6, sm_t6[tid * 12 + v]);
        size_t base = ((size_t)(p0 + tid) * NB_D + nb) * 6;
        #pragma unroll
        for (int j = 0; j < 6; ++j) g_cand[base + j] = t6[j];
    }
}

// ---------------- topk merge + score + loss -----------------------------------
__global__ void topk_kernel(const float* __restrict__ r_in, float* __restrict__ out) {
    int warp = threadIdx.x >> 5;
    int lane = threadIdx.x & 31;
    int p = blockIdx.x * 4 + warp;
    const float* cand = g_cand + (size_t)p * (NB_D * 6);   // 192 values

    float t6[6];
    #pragma unroll
    for (int j = 0; j < 6; ++j) t6[j] = 3.4e38f;
    #pragma unroll
    for (int j = 0; j < 6; ++j) insert6(t6, cand[lane + 32 * j]);

    #pragma unroll
    for (int off = 16; off > 0; off >>= 1) {
        float o6[6];
        #pragma unroll
        for (int j = 0; j < 6; ++j) o6[j] = __shfl_xor_sync(0xffffffffu, t6[j], off);
        #pragma unroll
        for (int j = 0; j < 6; ++j) insert6(t6, o6[j]);
    }

    if (lane == 0) {
        float rr = r_in[0];
        float r2 = rr * rr;
        float d0 = sqrtf(fmaxf(t6[0], 0.f));
        float d1 = sqrtf(fmaxf(t6[1], 0.f));
        float d2 = sqrtf(fmaxf(t6[2], 0.f));
        float w0 = 1.f / (1.f + expf(d0 - d1) + expf(d0 - d2));
        out[1 + p] = w0 * d0;

        float att = fmaxf(t6[0] - r2, 0.f) + fmaxf(t6[1] - r2, 0.f) + fmaxf(t6[2] - r2, 0.f);
        float rep = fmaxf(r2 - t6[3] - 0.1f, 0.f) + fmaxf(r2 - t6[4] - 0.1f, 0.f)
                  + fmaxf(r2 - t6[5] - 0.1f, 0.f);
        g_losspart[p] = att + rep;
    }
}

__global__ void loss_kernel(float* __restrict__ out) {
    __shared__ float sbuf[256];
    float s = 0.f;
    for (int i = threadIdx.x; i < M_TOT; i += 256) s += g_losspart[i];
    sbuf[threadIdx.x] = s;
    __syncthreads();
    for (int o = 128; o > 0; o >>= 1) {
        if (threadIdx.x < o) sbuf[threadIdx.x] += sbuf[threadIdx.x + o];
        __syncthreads();
    }
    if (threadIdx.x == 0)
        out[0] = sbuf[0] * (1000.f / (float)(M_TOT * 3));
}

// ---------------- launcher ------------------------------------------------------
extern "C" void kernel_launch(void* const* d_in, const int* in_sizes, int n_in,
                              void* d_out, int out_size) {
    const float* sample = (const float*)d_in[0];
    const float* W      = (const float*)d_in[1];
    const float* bias   = (const float*)d_in[2];
    const float* C      = (const float*)d_in[3];
    const float* r      = (const float*)d_in[4];
    float* out = (float*)d_out;

    cudaFuncSetAttribute(phi_mma, cudaFuncAttributeMaxDynamicSharedMemorySize, DYN_SMEM);
    cudaFuncSetAttribute(dist_mma, cudaFuncAttributeMaxDynamicSharedMemorySize, DYN_SMEM);

    prep_fused<<<NB_PREP, 256>>>(sample, W, C);                         // 0
    phi_mma<<<dim3(NB_P, M_TOT / 128), 256, DYN_SMEM>>>(W, bias);       // 1
    // pad slot 2 with a no-cost kernel? not needed — dist lands at index 2;
    // ncu -s 5 -c 1 samples launch index 5 of the harness run; keep order stable.
    dist_mma<<<dim3(NB_D, M_TOT / 128), 256, DYN_SMEM>>>();             // 2
    topk_kernel<<<M_TOT / 4, 128>>>(r, out);                            // 3
    loss_kernel<<<1, 256>>>(out);                                       // 4
}

// round 16
// speedup vs baseline: 1.0111x; 1.0043x over previous
#include <cuda_runtime.h>
#include <cuda_bf16.h>
#include <math.h>
#include <stdint.h>

#define DIMC   1792
#define M_TOT  16384        // 4 * 64 * 64
#define NCENT  4096
#define HW     4096
#define NB_D   32           // dist n-tiles of 128
#define NB_P   14           // phi  n-tiles of 128
#define KSTEPS 28           // 1792 / 64

// ---------------- scratch ---------------------------------------------------
__device__ __align__(1024) __nv_bfloat16 g_sample_t[(size_t)M_TOT * DIMC];
__device__ __align__(1024) __nv_bfloat16 g_phi_bf[(size_t)M_TOT * DIMC];
__device__ __align__(1024) __nv_bfloat16 g_Ct[(size_t)NCENT * DIMC];
__device__ __align__(1024) __nv_bfloat16 g_Wbf[(size_t)DIMC * DIMC];
__device__ float g_feat2p[M_TOT * NB_P];
__device__ float g_cnorm[NCENT];
__device__ float g_cand[(size_t)M_TOT * NB_D * 6];

// ---------------- helpers ----------------------------------------------------
__device__ __forceinline__ uint32_t smem_u32(const void* p) {
    uint32_t a;
    asm("{ .reg .u64 t; cvta.to.shared.u64 t, %1; cvt.u32.u64 %0, t; }" : "=r"(a) : "l"(p));
    return a;
}
__device__ __forceinline__ void cp16(uint32_t dst, const void* src) {
    asm volatile("cp.async.cg.shared.global [%0], [%1], 16;" :: "r"(dst), "l"(src));
}
__device__ __forceinline__ void insert6(float (&t)[6], float v) {
    if (v < t[5]) {
        t[5] = v;
        #pragma unroll
        for (int j = 5; j > 0; --j)
            if (t[j] < t[j-1]) { float tmp = t[j-1]; t[j-1] = t[j]; t[j] = tmp; }
    }
}

// stage: A(128 rows x 128B) + B(128 rows x 128B) = 32KB; 3 stages = 96KB
#define STG_BYTES 32768
#define B_OFF     16384
#define DYN_SMEM  (3 * STG_BYTES)
// full SW128 swizzle: row r (0..127, 128B pitch), 16B-chunk c (0..7)
__device__ __forceinline__ uint32_t swz(int r, int c) {
    return (uint32_t)(r * 128 + ((c ^ (r & 7)) * 16));
}

__device__ __forceinline__ void load_stage(uint32_t sb, int s,
                                           const __nv_bfloat16* A,
                                           const __nv_bfloat16* B,
                                           int k0, int tid) {
    uint32_t abase = sb + s * STG_BYTES;
    uint32_t bbase = abase + B_OFF;
    #pragma unroll
    for (int i = 0; i < 4; ++i) {           // A: 128 rows x 128B
        int slot = tid + i * 256;
        int r = slot >> 3, c = slot & 7;
        cp16(abase + swz(r, c), (const char*)A + ((size_t)r * DIMC + k0 + c * 8) * 2);
    }
    #pragma unroll
    for (int i = 0; i < 4; ++i) {           // B: 128 rows x 128B
        int slot = tid + i * 256;
        int r = slot >> 3, c = slot & 7;
        cp16(bbase + swz(r, c), (const char*)B + ((size_t)r * DIMC + k0 + c * 8) * 2);
    }
    asm volatile("cp.async.commit_group;" ::: "memory");
}

#define MMA_BF16(ac, a, b0, b1) \
    asm volatile( \
        "mma.sync.aligned.m16n8k16.row.col.f32.bf16.bf16.f32 " \
        "{%0,%1,%2,%3}, {%4,%5,%6,%7}, {%8,%9}, {%0,%1,%2,%3};" \
        : "+f"((ac)[0]), "+f"((ac)[1]), "+f"((ac)[2]), "+f"((ac)[3]) \
        : "r"((a)[0]), "r"((a)[1]), "r"((a)[2]), "r"((a)[3]), \
          "r"(b0), "r"(b1))

#define LDSM4(dst, addr) \
    asm volatile("ldmatrix.sync.aligned.m8n8.x4.shared.b16 {%0,%1,%2,%3}, [%4];" \
                 : "=r"((dst)[0]), "=r"((dst)[1]), "=r"((dst)[2]), "=r"((dst)[3]) \
                 : "r"(addr))

__device__ __forceinline__ uint32_t b_addr(uint32_t bbase, int wn, int lane,
                                           int ks, int nq) {
    int q = lane >> 3;
    int r = wn * 64 + nq * 16 + (q >> 1) * 8 + (lane & 7);
    int c = ks * 2 + (q & 1);
    return bbase + swz(r, c);
}

// ---------------- main GEMM: 128x128 tile, 8 warps (32x64 each), K=1792 ------
__device__ __forceinline__ void gemm_main(const __nv_bfloat16* A,
                                          const __nv_bfloat16* B,
                                          uint32_t sb,
                                          float (&acc)[2][8][4]) {
    int tid = threadIdx.x, lane = tid & 31, w = tid >> 5;
    int wm = w & 3, wn = w >> 2;

    load_stage(sb, 0, A, B, 0, tid);
    load_stage(sb, 1, A, B, 64, tid);
    asm volatile("cp.async.wait_group 1;" ::: "memory");
    __syncthreads();

    for (int kt = 0; kt < KSTEPS; ++kt) {
        int s = kt % 3;
        if (kt + 2 < KSTEPS)
            load_stage(sb, (kt + 2) % 3, A, B, (kt + 2) * 64, tid);
        else
            asm volatile("cp.async.commit_group;" ::: "memory");

        uint32_t abase = sb + s * STG_BYTES;
        uint32_t bbase = abase + B_OFF;

        uint32_t afr[2][2][4];   // [buf][mi][4]
        uint32_t bfr[2][4];      // [buf][4]
        #pragma unroll
        for (int mi = 0; mi < 2; ++mi) {
            int r = wm * 32 + mi * 16 + (lane & 15);
            int c = (lane >> 4);
            LDSM4(afr[0][mi], abase + swz(r, c));
        }
        LDSM4(bfr[0], b_addr(bbase, wn, lane, 0, 0));

        #pragma unroll
        for (int ks = 0; ks < 4; ++ks) {
            int cur = ks & 1;
            if (ks < 3) {
                #pragma unroll
                for (int mi = 0; mi < 2; ++mi) {
                    int r = wm * 32 + mi * 16 + (lane & 15);
                    int c = (ks + 1) * 2 + (lane >> 4);
                    LDSM4(afr[cur ^ 1][mi], abase + swz(r, c));
                }
            }
            #pragma unroll
            for (int nq = 0; nq < 4; ++nq) {
                int bb = nq & 1;
                if (nq < 3)
                    LDSM4(bfr[bb ^ 1], b_addr(bbase, wn, lane, ks, nq + 1));
                else if (ks < 3)
                    LDSM4(bfr[bb ^ 1], b_addr(bbase, wn, lane, ks + 1, 0));
                MMA_BF16(acc[0][nq * 2],     afr[cur][0], bfr[bb][0], bfr[bb][1]);
                MMA_BF16(acc[1][nq * 2],     afr[cur][1], bfr[bb][0], bfr[bb][1]);
                MMA_BF16(acc[0][nq * 2 + 1], afr[cur][0], bfr[bb][2], bfr[bb][3]);
                MMA_BF16(acc[1][nq * 2 + 1], afr[cur][1], bfr[bb][2], bfr[bb][3]);
            }
        }
        asm volatile("cp.async.wait_group 1;" ::: "memory");
        __syncthreads();
    }
}

// ---------------- fused prepass -------------------------------------------------
#define NB_TS  14336
#define NB_TC  7168
#define NB_CW  1792
#define NB_CN  128
#define NB_PREP (NB_TS + NB_TC + NB_CW + NB_CN)

__global__ void prep_fused(const float* __restrict__ S,
                           const float* __restrict__ W,
                           const float* __restrict__ C,
                           float* __restrict__ out) {
    __shared__ float t[32][65];
    int idx = blockIdx.x;
    int tid = threadIdx.x;

    if (idx == 0 && tid == 0) out[0] = 0.f;   // zero the loss accumulator

    if (idx < NB_TS) {
        // ---- transpose_sample: tile 32 hw x 64 c ----
        int bz = idx / 3584;
        int r = idx - bz * 3584;
        int bx = r & 127, by = r >> 7;
        int hw0 = bx * 32, c0 = by * 64;
        int tx = tid & 31, ty = tid >> 5;
        const float* src = S + ((size_t)bz * DIMC + c0) * HW + hw0;
        #pragma unroll
        for (int i = 0; i < 8; ++i) {
            int cr = ty + i * 8;
            t[tx][cr] = src[(size_t)cr * HW + tx];
        }
        __syncthreads();
        __nv_bfloat16* dst = g_sample_t + ((size_t)bz * HW + hw0) * DIMC + c0;
        #pragma unroll
        for (int i = 0; i < 4; ++i) {
            int hw = ty + i * 8;
            __nv_bfloat162 v = __floats2bfloat162_rn(t[hw][tx * 2], t[hw][tx * 2 + 1]);
            *(__nv_bfloat162*)&dst[(size_t)hw * DIMC + tx * 2] = v;
        }
    } else if (idx < NB_TS + NB_TC) {
        // ---- transpose_C: tile 32 k x 32 c ----
        int j = idx - NB_TS;
        int k0 = (j & 127) * 32, c0 = (j >> 7) * 32;
        int tx = tid & 31, ty = tid >> 5;
        #pragma unroll
        for (int i = 0; i < 4; ++i)
            t[ty + i * 8][tx] = C[(size_t)(c0 + ty + i * 8) * NCENT + k0 + tx];
        __syncthreads();
        #pragma unroll
        for (int i = 0; i < 4; ++i)
            g_Ct[(size_t)(k0 + ty + i * 8) * DIMC + c0 + tx] =
                __float2bfloat16(t[tx][ty + i * 8]);
    } else if (idx < NB_TS + NB_TC + NB_CW) {
        // ---- convert_W ----
        int o = idx - (NB_TS + NB_TC);
        for (int c = tid; c < DIMC; c += 256)
            g_Wbf[(size_t)o * DIMC + c] = __float2bfloat16(W[(size_t)o * 1794 + c]);
    } else {
        // ---- cnorm: 32 centers per block, 8-way c split, bf16-rounded ----
        int b = idx - (NB_TS + NB_TC + NB_CW);
        int k = b * 32 + (tid & 31);
        int ch = tid >> 5;
        float s = 0.f;
        int cbeg = ch * 224;
        for (int c = cbeg; c < cbeg + 224; ++c) {
            float v = __bfloat162float(__float2bfloat16(C[(size_t)c * NCENT + k]));
            s += v * v;
        }
        float* red = &t[0][0];
        red[(tid & 31) * 8 + ch] = s;
        __syncthreads();
        if (tid < 32) {
            float a = 0.f;
            #pragma unroll
            for (int j2 = 0; j2 < 8; ++j2) a += red[tid * 8 + j2];
            g_cnorm[b * 32 + tid] = a;
        }
    }
}

// ---------------- phi GEMM (coordconv 1x1) ------------------------------------
__global__ __launch_bounds__(256, 2) void phi_mma(const float* __restrict__ W,
                                                  const float* __restrict__ bias) {
    extern __shared__ __align__(1024) unsigned char smem[];
    uint32_t sb = smem_u32(smem);
    const int n0 = blockIdx.x * 128;
    const int p0 = blockIdx.y * 128;

    float acc[2][8][4] = {};
    gemm_main(g_sample_t + (size_t)p0 * DIMC, g_Wbf + (size_t)n0 * DIMC, sb, acc);

    int tid = threadIdx.x, lane = tid & 31, w = tid >> 5;
    int wm = w & 3, wn = w >> 2, gid = lane >> 2, tq = lane & 3;

    float* smw = (float*)smem;            // [128]wx [128]wy [128]b
    float* smf = (float*)(smem + 2048);   // [128][2]
    if (tid < 128) {
        size_t col = (size_t)(n0 + tid);
        smw[tid]       = __ldg(&W[col * 1794 + 1792]);
        smw[128 + tid] = __ldg(&W[col * 1794 + 1793]);
        smw[256 + tid] = __ldg(&bias[col]);
    }
    __syncthreads();

    #pragma unroll
    for (int mi = 0; mi < 2; ++mi)
        #pragma unroll
        for (int hh = 0; hh < 2; ++hh) {
            int row = wm * 32 + mi * 16 + hh * 8 + gid;
            int p = p0 + row;
            int hw = p & 4095;
            float xx = -1.f + 2.f * (float)(hw & 63) * (1.f / 63.f);
            float yy = -1.f + 2.f * (float)(hw >> 6) * (1.f / 63.f);
            float sq = 0.f;
            #pragma unroll
            for (int ni = 0; ni < 8; ++ni) {
                int ci = wn * 64 + ni * 8 + tq * 2;
                float v0 = acc[mi][ni][hh * 2]     + xx * smw[ci]   + yy * smw[128 + ci]   + smw[256 + ci];
                float v1 = acc[mi][ni][hh * 2 + 1] + xx * smw[ci+1] + yy * smw[128 + ci+1] + smw[256 + ci+1];
                __nv_bfloat162 bb = __floats2bfloat162_rn(v0, v1);
                *(uint32_t*)&g_phi_bf[(size_t)p * DIMC + n0 + ci] = *(uint32_t*)&bb;
                float f0 = __bfloat162float(bb.x), f1 = __bfloat162float(bb.y);
                sq += f0 * f0 + f1 * f1;
            }
            sq += __shfl_xor_sync(0xffffffffu, sq, 1);
            sq += __shfl_xor_sync(0xffffffffu, sq, 2);
            if (tq == 0) smf[row * 2 + wn] = sq;
        }
    __syncthreads();
    if (tid < 128)
        g_feat2p[(size_t)(p0 + tid) * NB_P + blockIdx.x] = smf[tid * 2] + smf[tid * 2 + 1];
}

// ---------------- dist GEMM + per-tile top-6 (feat2 folded in) ------------------
__global__ __launch_bounds__(256, 2) void dist_mma() {
    extern __shared__ __align__(1024) unsigned char smem[];
    uint32_t sb = smem_u32(smem);
    const int nb = blockIdx.x;
    const int n0 = nb * 128;
    const int p0 = blockIdx.y * 128;

    float acc[2][8][4] = {};
    gemm_main(g_phi_bf + (size_t)p0 * DIMC, g_Ct + (size_t)n0 * DIMC, sb, acc);

    int tid = threadIdx.x, lane = tid & 31, w = tid >> 5;
    int wm = w & 3, wn = w >> 2, gid = lane >> 2, tq = lane & 3;

    float f2r[2][2];
    #pragma unroll
    for (int mi = 0; mi < 2; ++mi)
        #pragma unroll
        for (int hh = 0; hh < 2; ++hh) {
            int row = wm * 32 + mi * 16 + hh * 8 + gid;
            const float* fp = &g_feat2p[(size_t)(p0 + row) * NB_P];
            float s = 0.f;
            #pragma unroll
            for (int i = 0; i < NB_P; ++i) s += fp[i];
            f2r[mi][hh] = s;
        }

    float* smc = (float*)smem;                 // [128] cnorm
    float* sm_t6 = (float*)(smem + 1024);      // [128][2][6]
    if (tid < 128) smc[tid] = g_cnorm[n0 + tid];
    __syncthreads();

    #pragma unroll
    for (int mi = 0; mi < 2; ++mi)
        #pragma unroll
        for (int hh = 0; hh < 2; ++hh) {
            int row = wm * 32 + mi * 16 + hh * 8 + gid;
            float f2 = f2r[mi][hh];
            float t6[6];
            #pragma unroll
            for (int j = 0; j < 6; ++j) t6[j] = 3.4e38f;
            #pragma unroll
            for (int ni = 0; ni < 8; ++ni) {
                int ci = wn * 64 + ni * 8 + tq * 2;
                insert6(t6, f2 + smc[ci]     - 2.f * acc[mi][ni][hh * 2]);
                insert6(t6, f2 + smc[ci + 1] - 2.f * acc[mi][ni][hh * 2 + 1]);
            }
            #pragma unroll
            for (int off = 1; off <= 2; off <<= 1) {
                float o6[6];
                #pragma unroll
                for (int j = 0; j < 6; ++j) o6[j] = __shfl_xor_sync(0xffffffffu, t6[j], off);
                #pragma unroll
                for (int j = 0; j < 6; ++j) insert6(t6, o6[j]);
            }
            if (tq == 0) {
                #pragma unroll
                for (int j = 0; j < 6; ++j) sm_t6[(row * 2 + wn) * 6 + j] = t6[j];
            }
        }
    __syncthreads();
    if (tid < 128) {
        float t6[6];
        #pragma unroll
        for (int j = 0; j < 6; ++j) t6[j] = 3.4e38f;
        #pragma unroll
        for (int v = 0; v < 12; ++v) insert6(t6, sm_t6[tid * 12 + v]);
        size_t base = ((size_t)(p0 + tid) * NB_D + nb) * 6;
        #pragma unroll
        for (int j = 0; j < 6; ++j) g_cand[base + j] = t6[j];
    }
}

// ---------------- topk merge + score + fused loss reduce ------------------------
__global__ void topk_kernel(const float* __restrict__ r_in, float* __restrict__ out) {
    __shared__ float lbuf[4];
    int warp = threadIdx.x >> 5;
    int lane = threadIdx.x & 31;
    int p = blockIdx.x * 4 + warp;
    const float* cand = g_cand + (size_t)p * (NB_D * 6);   // 192 values

    float t6[6];
    #pragma unroll
    for (int j = 0; j < 6; ++j) t6[j] = 3.4e38f;
    #pragma unroll
    for (int j = 0; j < 6; ++j) insert6(t6, cand[lane + 32 * j]);

    #pragma unroll
    for (int off = 16; off > 0; off >>= 1) {
        float o6[6];
        #pragma unroll
        for (int j = 0; j < 6; ++j) o6[j] = __shfl_xor_sync(0xffffffffu, t6[j], off);
        #pragma unroll
        for (int j = 0; j < 6; ++j) insert6(t6, o6[j]);
    }

    if (lane == 0) {
        float rr = r_in[0];
        float r2 = rr * rr;
        float d0 = sqrtf(fmaxf(t6[0], 0.f));
        float d1 = sqrtf(fmaxf(t6[1], 0.f));
        float d2 = sqrtf(fmaxf(t6[2], 0.f));
        float w0 = 1.f / (1.f + expf(d0 - d1) + expf(d0 - d2));
        out[1 + p] = w0 * d0;

        float att = fmaxf(t6[0] - r2, 0.f) + fmaxf(t6[1] - r2, 0.f) + fmaxf(t6[2] - r2, 0.f);
        float rep = fmaxf(r2 - t6[3] - 0.1f, 0.f) + fmaxf(r2 - t6[4] - 0.1f, 0.f)
                  + fmaxf(r2 - t6[5] - 0.1f, 0.f);
        lbuf[warp] = att + rep;
    }
    __syncthreads();
    if (threadIdx.x == 0) {
        float s = (lbuf[0] + lbuf[1]) + (lbuf[2] + lbuf[3]);
        atomicAdd(out, s * (1000.f / (float)(M_TOT * 3)));   // (1/NU)*mean scale
    }
}

// ---------------- launcher ------------------------------------------------------
extern "C" void kernel_launch(void* const* d_in, const int* in_sizes, int n_in,
                              void* d_out, int out_size) {
    const float* sample = (const float*)d_in[0];
    const float* W      = (const float*)d_in[1];
    const float* bias   = (const float*)d_in[2];
    const float* C      = (const float*)d_in[3];
    const float* r      = (const float*)d_in[4];
    float* out = (float*)d_out;

    cudaFuncSetAttribute(phi_mma, cudaFuncAttributeMaxDynamicSharedMemorySize, DYN_SMEM);
    cudaFuncSetAttribute(dist_mma, cudaFuncAttributeMaxDynamicSharedMemorySize, DYN_SMEM);

    prep_fused<<<NB_PREP, 256>>>(sample, W, C, out);                    // 0
    phi_mma<<<dim3(NB_P, M_TOT / 128), 256, DYN_SMEM>>>(W, bias);       // 1
    dist_mma<<<dim3(NB_D, M_TOT / 128), 256, DYN_SMEM>>>();             // 2
    topk_kernel<<<M_TOT / 4, 128>>>(r, out);                            // 3
}

// round 17
// speedup vs baseline: 1.0178x; 1.0066x over previous
#include <cuda_runtime.h>
#include <cuda_bf16.h>
#include <math.h>
#include <stdint.h>

#define DIMC   1792
#define M_TOT  16384        // 4 * 64 * 64
#define NCENT  4096
#define HW     4096
#define NB_D   32           // dist n-tiles of 128
#define NB_P   14           // phi  n-tiles of 128
#define KSTEPS 28           // 1792 / 64

// ---------------- scratch ---------------------------------------------------
__device__ __align__(1024) __nv_bfloat16 g_sample_t[(size_t)M_TOT * DIMC];
__device__ __align__(1024) __nv_bfloat16 g_phi_bf[(size_t)M_TOT * DIMC];
__device__ __align__(1024) __nv_bfloat16 g_Ct[(size_t)NCENT * DIMC];
__device__ __align__(1024) __nv_bfloat16 g_Wbf[(size_t)DIMC * DIMC];
__device__ float g_feat2p[M_TOT * NB_P];
__device__ float g_cnorm[NCENT];
__device__ float g_cand[(size_t)M_TOT * NB_D * 6];

// ---------------- helpers ----------------------------------------------------
__device__ __forceinline__ uint32_t smem_u32(const void* p) {
    uint32_t a;
    asm("{ .reg .u64 t; cvta.to.shared.u64 t, %1; cvt.u32.u64 %0, t; }" : "=r"(a) : "l"(p));
    return a;
}
__device__ __forceinline__ void cp16(uint32_t dst, const void* src) {
    asm volatile("cp.async.cg.shared.global [%0], [%1], 16;" :: "r"(dst), "l"(src));
}
__device__ __forceinline__ void insert6(float (&t)[6], float v) {
    if (v < t[5]) {
        t[5] = v;
        #pragma unroll
        for (int j = 5; j > 0; --j)
            if (t[j] < t[j-1]) { float tmp = t[j-1]; t[j-1] = t[j]; t[j] = tmp; }
    }
}

// stage: A(128 rows x 128B) + B(128 rows x 128B) = 32KB; 3 stages = 96KB
#define STG_BYTES 32768
#define B_OFF     16384
#define DYN_SMEM  (3 * STG_BYTES)
// full SW128 swizzle: row r (0..127, 128B pitch), 16B-chunk c (0..7)
__device__ __forceinline__ uint32_t swz(int r, int c) {
    return (uint32_t)(r * 128 + ((c ^ (r & 7)) * 16));
}

__device__ __forceinline__ void load_stage(uint32_t sb, int s,
                                           const __nv_bfloat16* A,
                                           const __nv_bfloat16* B,
                                           int k0, int tid) {
    uint32_t abase = sb + s * STG_BYTES;
    uint32_t bbase = abase + B_OFF;
    #pragma unroll
    for (int i = 0; i < 4; ++i) {           // A: 128 rows x 128B
        int slot = tid + i * 256;
        int r = slot >> 3, c = slot & 7;
        cp16(abase + swz(r, c), (const char*)A + ((size_t)r * DIMC + k0 + c * 8) * 2);
    }
    #pragma unroll
    for (int i = 0; i < 4; ++i) {           // B: 128 rows x 128B
        int slot = tid + i * 256;
        int r = slot >> 3, c = slot & 7;
        cp16(bbase + swz(r, c), (const char*)B + ((size_t)r * DIMC + k0 + c * 8) * 2);
    }
    asm volatile("cp.async.commit_group;" ::: "memory");
}

#define MMA_BF16(ac, a, b0, b1) \
    asm volatile( \
        "mma.sync.aligned.m16n8k16.row.col.f32.bf16.bf16.f32 " \
        "{%0,%1,%2,%3}, {%4,%5,%6,%7}, {%8,%9}, {%0,%1,%2,%3};" \
        : "+f"((ac)[0]), "+f"((ac)[1]), "+f"((ac)[2]), "+f"((ac)[3]) \
        : "r"((a)[0]), "r"((a)[1]), "r"((a)[2]), "r"((a)[3]), \
          "r"(b0), "r"(b1))

#define LDSM4(dst, addr) \
    asm volatile("ldmatrix.sync.aligned.m8n8.x4.shared.b16 {%0,%1,%2,%3}, [%4];" \
                 : "=r"((dst)[0]), "=r"((dst)[1]), "=r"((dst)[2]), "=r"((dst)[3]) \
                 : "r"(addr))

__device__ __forceinline__ uint32_t b_addr(uint32_t bbase, int wn, int lane,
                                           int ks, int nq) {
    int q = lane >> 3;
    int r = wn * 64 + nq * 16 + (q >> 1) * 8 + (lane & 7);
    int c = ks * 2 + (q & 1);
    return bbase + swz(r, c);
}

// ---------------- main GEMM: 128x128 tile, 8 warps (32x64 each), K=1792 ------
__device__ __forceinline__ void gemm_main(const __nv_bfloat16* A,
                                          const __nv_bfloat16* B,
                                          uint32_t sb,
                                          float (&acc)[2][8][4]) {
    int tid = threadIdx.x, lane = tid & 31, w = tid >> 5;
    int wm = w & 3, wn = w >> 2;

    load_stage(sb, 0, A, B, 0, tid);
    load_stage(sb, 1, A, B, 64, tid);
    asm volatile("cp.async.wait_group 1;" ::: "memory");
    __syncthreads();

    for (int kt = 0; kt < KSTEPS; ++kt) {
        int s = kt % 3;
        if (kt + 2 < KSTEPS)
            load_stage(sb, (kt + 2) % 3, A, B, (kt + 2) * 64, tid);
        else
            asm volatile("cp.async.commit_group;" ::: "memory");

        uint32_t abase = sb + s * STG_BYTES;
        uint32_t bbase = abase + B_OFF;

        uint32_t afr[2][2][4];   // [buf][mi][4]
        uint32_t bfr[2][4];      // [buf][4]
        #pragma unroll
        for (int mi = 0; mi < 2; ++mi) {
            int r = wm * 32 + mi * 16 + (lane & 15);
            int c = (lane >> 4);
            LDSM4(afr[0][mi], abase + swz(r, c));
        }
        LDSM4(bfr[0], b_addr(bbase, wn, lane, 0, 0));

        #pragma unroll
        for (int ks = 0; ks < 4; ++ks) {
            int cur = ks & 1;
            if (ks < 3) {
                #pragma unroll
                for (int mi = 0; mi < 2; ++mi) {
                    int r = wm * 32 + mi * 16 + (lane & 15);
                    int c = (ks + 1) * 2 + (lane >> 4);
                    LDSM4(afr[cur ^ 1][mi], abase + swz(r, c));
                }
            }
            #pragma unroll
            for (int nq = 0; nq < 4; ++nq) {
                int bb = nq & 1;
                if (nq < 3)
                    LDSM4(bfr[bb ^ 1], b_addr(bbase, wn, lane, ks, nq + 1));
                else if (ks < 3)
                    LDSM4(bfr[bb ^ 1], b_addr(bbase, wn, lane, ks + 1, 0));
                MMA_BF16(acc[0][nq * 2],     afr[cur][0], bfr[bb][0], bfr[bb][1]);
                MMA_BF16(acc[1][nq * 2],     afr[cur][1], bfr[bb][0], bfr[bb][1]);
                MMA_BF16(acc[0][nq * 2 + 1], afr[cur][0], bfr[bb][2], bfr[bb][3]);
                MMA_BF16(acc[1][nq * 2 + 1], afr[cur][1], bfr[bb][2], bfr[bb][3]);
            }
        }
        asm volatile("cp.async.wait_group 1;" ::: "memory");
        __syncthreads();
    }
}

// ---------------- fused prepass -------------------------------------------------
#define NB_TS  14336
#define NB_TC  7168
#define NB_CW  1792
#define NB_CN  128
#define NB_PREP (NB_TS + NB_TC + NB_CW + NB_CN)

__global__ void prep_fused(const float* __restrict__ S,
                           const float* __restrict__ W,
                           const float* __restrict__ C,
                           float* __restrict__ out) {
    __shared__ float t[32][65];
    int idx = blockIdx.x;
    int tid = threadIdx.x;

    if (idx == 0 && tid == 0) out[0] = 0.f;   // zero the loss accumulator

    if (idx < NB_TS) {
        // ---- transpose_sample: tile 32 hw x 64 c ----
        int bz = idx / 3584;
        int r = idx - bz * 3584;
        int bx = r & 127, by = r >> 7;
        int hw0 = bx * 32, c0 = by * 64;
        int tx = tid & 31, ty = tid >> 5;
        const float* src = S + ((size_t)bz * DIMC + c0) * HW + hw0;
        #pragma unroll
        for (int i = 0; i < 8; ++i) {
            int cr = ty + i * 8;
            t[tx][cr] = src[(size_t)cr * HW + tx];
        }
        __syncthreads();
        __nv_bfloat16* dst = g_sample_t + ((size_t)bz * HW + hw0) * DIMC + c0;
        #pragma unroll
        for (int i = 0; i < 4; ++i) {
            int hw = ty + i * 8;
            __nv_bfloat162 v = __floats2bfloat162_rn(t[hw][tx * 2], t[hw][tx * 2 + 1]);
            *(__nv_bfloat162*)&dst[(size_t)hw * DIMC + tx * 2] = v;
        }
    } else if (idx < NB_TS + NB_TC) {
        // ---- transpose_C: tile 32 k x 32 c ----
        int j = idx - NB_TS;
        int k0 = (j & 127) * 32, c0 = (j >> 7) * 32;
        int tx = tid & 31, ty = tid >> 5;
        #pragma unroll
        for (int i = 0; i < 4; ++i)
            t[ty + i * 8][tx] = C[(size_t)(c0 + ty + i * 8) * NCENT + k0 + tx];
        __syncthreads();
        #pragma unroll
        for (int i = 0; i < 4; ++i)
            g_Ct[(size_t)(k0 + ty + i * 8) * DIMC + c0 + tx] =
                __float2bfloat16(t[tx][ty + i * 8]);
    } else if (idx < NB_TS + NB_TC + NB_CW) {
        // ---- convert_W ----
        int o = idx - (NB_TS + NB_TC);
        for (int c = tid; c < DIMC; c += 256)
            g_Wbf[(size_t)o * DIMC + c] = __float2bfloat16(W[(size_t)o * 1794 + c]);
    } else {
        // ---- cnorm: 32 centers per block, 8-way c split, bf16-rounded ----
        int b = idx - (NB_TS + NB_TC + NB_CW);
        int k = b * 32 + (tid & 31);
        int ch = tid >> 5;
        float s = 0.f;
        int cbeg = ch * 224;
        for (int c = cbeg; c < cbeg + 224; ++c) {
            float v = __bfloat162float(__float2bfloat16(C[(size_t)c * NCENT + k]));
            s += v * v;
        }
        float* red = &t[0][0];
        red[(tid & 31) * 8 + ch] = s;
        __syncthreads();
        if (tid < 32) {
            float a = 0.f;
            #pragma unroll
            for (int j2 = 0; j2 < 8; ++j2) a += red[tid * 8 + j2];
            g_cnorm[b * 32 + tid] = a;
        }
    }
}

// ---------------- phi GEMM (coordconv 1x1) ------------------------------------
__global__ __launch_bounds__(256, 2) void phi_mma(const float* __restrict__ W,
                                                  const float* __restrict__ bias) {
    extern __shared__ __align__(1024) unsigned char smem[];
    uint32_t sb = smem_u32(smem);
    const int n0 = blockIdx.x * 128;
    const int p0 = blockIdx.y * 128;

    float acc[2][8][4] = {};
    gemm_main(g_sample_t + (size_t)p0 * DIMC, g_Wbf + (size_t)n0 * DIMC, sb, acc);

    int tid = threadIdx.x, lane = tid & 31, w = tid >> 5;
    int wm = w & 3, wn = w >> 2, gid = lane >> 2, tq = lane & 3;

    float* smw = (float*)smem;            // [128]wx [128]wy [128]b
    float* smf = (float*)(smem + 2048);   // [128][2]
    if (tid < 128) {
        size_t col = (size_t)(n0 + tid);
        smw[tid]       = __ldg(&W[col * 1794 + 1792]);
        smw[128 + tid] = __ldg(&W[col * 1794 + 1793]);
        smw[256 + tid] = __ldg(&bias[col]);
    }
    __syncthreads();

    #pragma unroll
    for (int mi = 0; mi < 2; ++mi)
        #pragma unroll
        for (int hh = 0; hh < 2; ++hh) {
            int row = wm * 32 + mi * 16 + hh * 8 + gid;
            int p = p0 + row;
            int hw = p & 4095;
            float xx = -1.f + 2.f * (float)(hw & 63) * (1.f / 63.f);
            float yy = -1.f + 2.f * (float)(hw >> 6) * (1.f / 63.f);
            float sq = 0.f;
            #pragma unroll
            for (int ni = 0; ni < 8; ++ni) {
                int ci = wn * 64 + ni * 8 + tq * 2;
                float v0 = acc[mi][ni][hh * 2]     + xx * smw[ci]   + yy * smw[128 + ci]   + smw[256 + ci];
                float v1 = acc[mi][ni][hh * 2 + 1] + xx * smw[ci+1] + yy * smw[128 + ci+1] + smw[256 + ci+1];
                __nv_bfloat162 bb = __floats2bfloat162_rn(v0, v1);
                *(uint32_t*)&g_phi_bf[(size_t)p * DIMC + n0 + ci] = *(uint32_t*)&bb;
                float f0 = __bfloat162float(bb.x), f1 = __bfloat162float(bb.y);
                sq += f0 * f0 + f1 * f1;
            }
            sq += __shfl_xor_sync(0xffffffffu, sq, 1);
            sq += __shfl_xor_sync(0xffffffffu, sq, 2);
            if (tq == 0) smf[row * 2 + wn] = sq;
        }
    __syncthreads();
    if (tid < 128)
        g_feat2p[(size_t)(p0 + tid) * NB_P + blockIdx.x] = smf[tid * 2] + smf[tid * 2 + 1];
}

// ---------------- dist GEMM + per-tile top-6 (feat2 folded in) ------------------
__global__ __launch_bounds__(256, 2) void dist_mma() {
    extern __shared__ __align__(1024) unsigned char smem[];
    uint32_t sb = smem_u32(smem);
    const int nb = blockIdx.x;
    const int n0 = nb * 128;
    const int p0 = blockIdx.y * 128;

    float acc[2][8][4] = {};
    gemm_main(g_phi_bf + (size_t)p0 * DIMC, g_Ct + (size_t)n0 * DIMC, sb, acc);

    int tid = threadIdx.x, lane = tid & 31, w = tid >> 5;
    int wm = w & 3, wn = w >> 2, gid = lane >> 2, tq = lane & 3;

    float f2r[2][2];
    #pragma unroll
    for (int mi = 0; mi < 2; ++mi)
        #pragma unroll
        for (int hh = 0; hh < 2; ++hh) {
            int row = wm * 32 + mi * 16 + hh * 8 + gid;
            const float* fp = &g_feat2p[(size_t)(p0 + row) * NB_P];
            float s = 0.f;
            #pragma unroll
            for (int i = 0; i < NB_P; ++i) s += fp[i];
            f2r[mi][hh] = s;
        }

    float* smc = (float*)smem;                 // [128] cnorm
    float* sm_t6 = (float*)(smem + 1024);      // [128][2][6]
    if (tid < 128) smc[tid] = g_cnorm[n0 + tid];
    __syncthreads();

    #pragma unroll
    for (int mi = 0; mi < 2; ++mi)
        #pragma unroll
        for (int hh = 0; hh < 2; ++hh) {
            int row = wm * 32 + mi * 16 + hh * 8 + gid;
            float f2 = f2r[mi][hh];
            float t6[6];
            #pragma unroll
            for (int j = 0; j < 6; ++j) t6[j] = 3.4e38f;
            #pragma unroll
            for (int ni = 0; ni < 8; ++ni) {
                int ci = wn * 64 + ni * 8 + tq * 2;
                insert6(t6, f2 + smc[ci]     - 2.f * acc[mi][ni][hh * 2]);
                insert6(t6, f2 + smc[ci + 1] - 2.f * acc[mi][ni][hh * 2 + 1]);
            }
            #pragma unroll
            for (int off = 1; off <= 2; off <<= 1) {
                float o6[6];
                #pragma unroll
                for (int j = 0; j < 6; ++j) o6[j] = __shfl_xor_sync(0xffffffffu, t6[j], off);
                #pragma unroll
                for (int j = 0; j < 6; ++j) insert6(t6, o6[j]);
            }
            if (tq == 0) {
                #pragma unroll
                for (int j = 0; j < 6; ++j) sm_t6[(row * 2 + wn) * 6 + j] = t6[j];
            }
        }
    __syncthreads();
    if (tid < 128) {
        float t6[6];
        #pragma unroll
        for (int j = 0; j < 6; ++j) t6[j] = 3.4e38f;
        #pragma unroll
        for (int v = 0; v < 12; ++v) insert6(t6, sm_t6[tid * 12 + v]);
        size_t base = ((size_t)(p0 + tid) * NB_D + nb) * 6;
        #pragma unroll
        for (int j = 0; j < 6; ++j) g_cand[base + j] = t6[j];
    }
}

// ---------------- topk: bitonic branch-free merge + score + fused loss ----------
#define CEX(i, j) { float lo = fminf(v[i], v[j]); float hi = fmaxf(v[i], v[j]); \
                    v[i] = lo; v[j] = hi; }

__global__ void topk_kernel(const float* __restrict__ r_in, float* __restrict__ out) {
    __shared__ float lbuf[4];
    int warp = threadIdx.x >> 5;
    int lane = threadIdx.x & 31;
    int p = blockIdx.x * 4 + warp;
    const float* cand = g_cand + (size_t)p * (NB_D * 6);   // 192 values

    // per-lane sorted-8 (6 real + 2 sentinels), ascending
    float v[8];
    #pragma unroll
    for (int j = 0; j < 6; ++j) v[j] = cand[lane + 32 * j];
    v[6] = 3.4e38f; v[7] = 3.4e38f;
    // Batcher odd-even mergesort for 8 (19 CE)
    CEX(0,1) CEX(2,3) CEX(4,5) CEX(6,7)
    CEX(0,2) CEX(1,3) CEX(4,6) CEX(5,7)
    CEX(1,2) CEX(5,6)
    CEX(0,4) CEX(1,5) CEX(2,6) CEX(3,7)
    CEX(2,4) CEX(3,5)
    CEX(1,2) CEX(3,4) CEX(5,6)

    // butterfly: 8-smallest-of-union via bitonic lower half + bitonic merge
    #pragma unroll
    for (int off = 16; off > 0; off >>= 1) {
        float o[8];
        #pragma unroll
        for (int j = 0; j < 8; ++j) o[j] = __shfl_xor_sync(0xffffffffu, v[j], off);
        float m[8];
        #pragma unroll
        for (int j = 0; j < 8; ++j) m[j] = fminf(v[j], o[7 - j]);
        #pragma unroll
        for (int j = 0; j < 8; ++j) v[j] = m[j];
        // bitonic merge network (sorts a bitonic 8-sequence): 12 CE
        CEX(0,4) CEX(1,5) CEX(2,6) CEX(3,7)
        CEX(0,2) CEX(1,3) CEX(4,6) CEX(5,7)
        CEX(0,1) CEX(2,3) CEX(4,5) CEX(6,7)
    }

    if (lane == 0) {
        float rr = r_in[0];
        float r2 = rr * rr;
        float d0 = sqrtf(fmaxf(v[0], 0.f));
        float d1 = sqrtf(fmaxf(v[1], 0.f));
        float d2 = sqrtf(fmaxf(v[2], 0.f));
        float w0 = 1.f / (1.f + expf(d0 - d1) + expf(d0 - d2));
        out[1 + p] = w0 * d0;

        float att = fmaxf(v[0] - r2, 0.f) + fmaxf(v[1] - r2, 0.f) + fmaxf(v[2] - r2, 0.f);
        float rep = fmaxf(r2 - v[3] - 0.1f, 0.f) + fmaxf(r2 - v[4] - 0.1f, 0.f)
                  + fmaxf(r2 - v[5] - 0.1f, 0.f);
        lbuf[warp] = att + rep;
    }
    __syncthreads();
    if (threadIdx.x == 0) {
        float s = (lbuf[0] + lbuf[1]) + (lbuf[2] + lbuf[3]);
        atomicAdd(out, s * (1000.f / (float)(M_TOT * 3)));   // (1/NU)*mean scale
    }
}

// ---------------- launcher ------------------------------------------------------
extern "C" void kernel_launch(void* const* d_in, const int* in_sizes, int n_in,
                              void* d_out, int out_size) {
    const float* sample = (const float*)d_in[0];
    const float* W      = (const float*)d_in[1];
    const float* bias   = (const float*)d_in[2];
    const float* C      = (const float*)d_in[3];
    const float* r      = (const float*)d_in[4];
    float* out = (float*)d_out;

    cudaFuncSetAttribute(phi_mma, cudaFuncAttributeMaxDynamicSharedMemorySize, DYN_SMEM);
    cudaFuncSetAttribute(dist_mma, cudaFuncAttributeMaxDynamicSharedMemorySize, DYN_SMEM);

    prep_fused<<<NB_PREP, 256>>>(sample, W, C, out);                    // 0
    phi_mma<<<dim3(NB_P, M_TOT / 128), 256, DYN_SMEM>>>(W, bias);       // 1
    dist_mma<<<dim3(NB_D, M_TOT / 128), 256, DYN_SMEM>>>();             // 2
    topk_kernel<<<M_TOT / 4, 128>>>(r, out);                            // 3
}